// round 7
// baseline (speedup 1.0000x reference)
#include <cuda_runtime.h>
#include <cuda_bf16.h>
#include <math.h>
#include <stdint.h>

#define B 32
#define T 8192
#define H 192
#define BT (B*T)
#define BINS 10
#define TAILV 5.0f
#define NJ 29

// residual stream (f32) and bf16 hi/lo stream, layout [b][t][c]
__device__ float g_x[(size_t)BT*H];
__device__ __align__(16) __nv_bfloat16 g_yh[(size_t)BT*H];
__device__ __align__(16) __nv_bfloat16 g_yl[(size_t)BT*H];
// chunk-ordered pw weight image: [layer][chunk(6)][dtype(2)][o=192][seg(4)][8 bf16]
__device__ __align__(16) __nv_bfloat16 g_wr[3*6*2*192*32];
// padded proj weight image: [hi/lo][32][pad 200] bf16
__device__ __align__(16) __nv_bfloat16 g_pw[2*32*200];
// transposed depthwise weights: [layer][tap][c]
__device__ float g_dwt[3*3*192];

__device__ __forceinline__ float gelu_exact(float v){
    return 0.5f*v*(1.0f+erff(v*0.70710678118654752f));
}

__device__ __forceinline__ uint32_t smem_u32(const void* p){
    uint32_t a;
    asm("{ .reg .u64 t; cvta.to.shared.u64 t, %1; cvt.u32.u64 %0, t; }" : "=r"(a) : "l"(p));
    return a;
}

#define LDSM4(r, addr) \
    asm volatile("ldmatrix.sync.aligned.m8n8.x4.shared.b16 {%0,%1,%2,%3}, [%4];" \
        : "=r"((r)[0]),"=r"((r)[1]),"=r"((r)[2]),"=r"((r)[3]) : "r"(addr))

#define MMA16816(d, a, b0, b1) \
    asm volatile("mma.sync.aligned.m16n8k16.row.col.f32.bf16.bf16.f32 " \
        "{%0,%1,%2,%3},{%4,%5,%6,%7},{%8,%9},{%0,%1,%2,%3};" \
        : "+f"((d)[0]),"+f"((d)[1]),"+f"((d)[2]),"+f"((d)[3]) \
        : "r"((a)[0]),"r"((a)[1]),"r"((a)[2]),"r"((a)[3]), "r"(b0),"r"(b1))

#define CP16(dst, src) \
    asm volatile("cp.async.cg.shared.global [%0], [%1], 16;" :: "r"(dst), "l"(src))
#define CP_COMMIT asm volatile("cp.async.commit_group;" ::: "memory")
#define CP_WAIT1  asm volatile("cp.async.wait_group 1;" ::: "memory")
#define CP_WAIT0  asm volatile("cp.async.wait_group 0;" ::: "memory")

// ---------------------------------------------------------------------------
__global__ void k_zero(float* __restrict__ out){
    out[(long long)B*2*T + threadIdx.x] = 0.0f;
}

// prep: pw chunk-ordered split image, proj split image, dw transpose
__global__ void k_prep(const float* __restrict__ pw_w,
                       const float* __restrict__ proj_w,
                       const float* __restrict__ dw_w)
{
    int i = blockIdx.x*256 + threadIdx.x;
    if (i < 3*H*H){
        int L = i / (H*H);
        int r = i - L*(H*H);
        int o = r / H, k = r - o*H;
        float w = pw_w[i];
        __nv_bfloat16 hb = __float2bfloat16(w);
        __nv_bfloat16 lb = __float2bfloat16(w - __bfloat162float(hb));
        int c = k >> 5;
        int s = (k >> 3) & 3;
        int j = k & 7;
        size_t base = ((size_t)(L*6 + c)*1536 + (size_t)o*4 + s)*8 + j;
        g_wr[base]          = hb;
        g_wr[base + 6144]   = lb;
    }
    if (i < 2*32*200){
        int p = i / 6400;
        int rem = i - p*6400;
        int r = rem / 200, c = rem - r*200;
        float w = (r < NJ && c < H) ? proj_w[r*H + c] : 0.0f;
        __nv_bfloat16 hb = __float2bfloat16(w);
        __nv_bfloat16 lb = __float2bfloat16(w - __bfloat162float(hb));
        g_pw[i] = p ? lb : hb;
    }
    if (i < 3*3*H){
        int L = i / (3*H);
        int rem = i - L*(3*H);
        int c = rem / 3, k = rem - c*3;
        g_dwt[L*(3*H) + k*H + c] = dw_w[i];
    }
}

// ---------------------------------------------------------------------------
// depthwise dilated conv (K=3) + LN + exact gelu -> bf16 hi/lo.
__global__ void __launch_bounds__(256) k_conv(int layer, int dil,
    const float* __restrict__ x,
    const float* __restrict__ in_w, const float* __restrict__ in_b,
    const float* __restrict__ xmask,
    const float* __restrict__ dw_b,
    const float* __restrict__ ln_g, const float* __restrict__ ln_b)
{
    int wid = threadIdx.x >> 5, lane = threadIdx.x & 31;
    long long g0 = (long long)blockIdx.x*32 + wid*4;
    int b = (int)(g0 >> 13);
    int t0 = (int)(g0 & (T-1));
    int c0 = lane*6;
    bool first = (layer == 0);

    float w0[6], w1[6], w2[6], bbv[6], ggv[6], gbv[6];
    {
        const float* wt = g_dwt + layer*(3*H);
        #pragma unroll
        for(int p=0;p<3;p++){
            float2 a = *(const float2*)(wt + c0 + p*2);
            w0[p*2]=a.x; w0[p*2+1]=a.y;
            float2 bq = *(const float2*)(wt + H + c0 + p*2);
            w1[p*2]=bq.x; w1[p*2+1]=bq.y;
            float2 cq = *(const float2*)(wt + 2*H + c0 + p*2);
            w2[p*2]=cq.x; w2[p*2+1]=cq.y;
            float2 d = *(const float2*)(dw_b + layer*H + c0 + p*2);
            bbv[p*2]=d.x; bbv[p*2+1]=d.y;
            float2 e = *(const float2*)(ln_g + layer*H + c0 + p*2);
            ggv[p*2]=e.x; ggv[p*2+1]=e.y;
            float2 f = *(const float2*)(ln_b + layer*H + c0 + p*2);
            gbv[p*2]=f.x; gbv[p*2+1]=f.y;
        }
    }
    float iw[6], ib[6];
    if(first){
        #pragma unroll
        for(int p=0;p<3;p++){
            float2 a = *(const float2*)(in_w + c0 + p*2);
            iw[p*2]=a.x; iw[p*2+1]=a.y;
            float2 bq = *(const float2*)(in_b + c0 + p*2);
            ib[p*2]=bq.x; ib[p*2+1]=bq.y;
        }
    }
    const float* mrow = xmask + (long long)b*T;
    const float* xrowa = x + ((long long)b*2)*T;

    #pragma unroll
    for(int tt=0;tt<4;tt++){
        long long row = g0 + tt;
        int t = t0 + tt;
        int tm = t - dil, tp = t + dil;
        bool hm = (tm >= 0), hp = (tp < T);
        float mm = hm ? mrow[tm] : 0.f;
        float m0 = mrow[t];
        float mp = hp ? mrow[tp] : 0.f;

        float xm[6], xz[6], xp[6];
        if(first){
            float xam = hm ? xrowa[tm] : 0.f;
            float xa0 = xrowa[t];
            float xap = hp ? xrowa[tp] : 0.f;
            #pragma unroll
            for(int k=0;k<6;k++){
                xm[k] = iw[k]*xam + ib[k];
                xz[k] = iw[k]*xa0 + ib[k];
                xp[k] = iw[k]*xap + ib[k];
            }
            float* gx = g_x + row*H + c0;
            #pragma unroll
            for(int p=0;p<3;p++)
                *(float2*)(gx + p*2) = make_float2(xz[p*2], xz[p*2+1]);
        } else {
            const float* base = g_x + row*H + c0;
            #pragma unroll
            for(int p=0;p<3;p++){
                float2 a = *(const float2*)(base + p*2);
                xz[p*2]=a.x; xz[p*2+1]=a.y;
            }
            if(hm){
                const float* bmp = base - (long long)dil*H;
                #pragma unroll
                for(int p=0;p<3;p++){
                    float2 a = *(const float2*)(bmp + p*2);
                    xm[p*2]=a.x; xm[p*2+1]=a.y;
                }
            } else {
                #pragma unroll
                for(int k=0;k<6;k++) xm[k]=0.f;
            }
            if(hp){
                const float* bpp = base + (long long)dil*H;
                #pragma unroll
                for(int p=0;p<3;p++){
                    float2 a = *(const float2*)(bpp + p*2);
                    xp[p*2]=a.x; xp[p*2+1]=a.y;
                }
            } else {
                #pragma unroll
                for(int k=0;k<6;k++) xp[k]=0.f;
            }
        }

        float v[6];
        float s=0.f, sq=0.f;
        #pragma unroll
        for(int k=0;k<6;k++){
            float r = w0[k]*(xm[k]*mm) + w1[k]*(xz[k]*m0) + w2[k]*(xp[k]*mp) + bbv[k];
            v[k]=r; s+=r; sq+=r*r;
        }
        #pragma unroll
        for(int o=16;o>0;o>>=1){
            s  += __shfl_xor_sync(0xffffffffu, s,  o);
            sq += __shfl_xor_sync(0xffffffffu, sq, o);
        }
        float mu = s*(1.0f/H);
        float rs = rsqrtf(sq*(1.0f/H) - mu*mu + 1e-5f);

        uint32_t hw[3], lw[3];
        #pragma unroll
        for(int p=0;p<3;p++){
            float y0 = gelu_exact((v[p*2]  -mu)*rs*ggv[p*2]   + gbv[p*2]);
            float y1 = gelu_exact((v[p*2+1]-mu)*rs*ggv[p*2+1] + gbv[p*2+1]);
            __nv_bfloat16 h0 = __float2bfloat16(y0);
            __nv_bfloat16 h1 = __float2bfloat16(y1);
            __nv_bfloat16 l0 = __float2bfloat16(y0 - __bfloat162float(h0));
            __nv_bfloat16 l1 = __float2bfloat16(y1 - __bfloat162float(h1));
            __nv_bfloat162 ph = __halves2bfloat162(h0,h1);
            __nv_bfloat162 pl = __halves2bfloat162(l0,l1);
            hw[p] = *(uint32_t*)&ph;
            lw[p] = *(uint32_t*)&pl;
        }
        uint32_t* oh = (uint32_t*)(g_yh + row*H + c0);
        uint32_t* ol = (uint32_t*)(g_yl + row*H + c0);
        oh[0]=hw[0]; oh[1]=hw[1]; oh[2]=hw[2];
        ol[0]=lw[0]; ol[1]=lw[1]; ol[2]=lw[2];
    }
}

// ---------------------------------------------------------------------------
// warp-MMA GEMM: D[t(64), o(192)] = Y . W^T, split-bf16, pass-separated
// MMA schedule (same-acc reuse distance 12). 256 threads, 8 warps (2Mx4N),
// A+B streamed via cp.async 2-stage rings -> 84.2KB smem -> 2 CTAs/SM.
#define BR      0
#define BSTG_D  15360
#define BSTG    30720
#define AR      61440
#define ASTG_D  5120
#define ASTG    10240
#define PAR_OFF 81920
#define GEMM_SMEM_BYTES (PAR_OFF + 2304)

__global__ void __launch_bounds__(256,2) k_gemm_mma(int layer, int last,
    const float* __restrict__ pw_b,
    const float* __restrict__ ln_g, const float* __restrict__ ln_b)
{
    extern __shared__ char smem[];
    uint32_t sbase = smem_u32(smem);
    int tid = threadIdx.x;
    int wid = tid >> 5, lane = tid & 31;
    int wm = wid & 1, wn = wid >> 1;        // 2 warps in M, 4 in N
    int q = lane >> 2, qi = lane & 3;
    long long bt0 = (long long)blockIdx.x * 64;

    float* par = (float*)(smem + PAR_OFF);
    if(tid < 192){
        par[tid]       = pw_b[layer*H + tid];
        par[192 + tid] = ln_g[layer*H + tid];
        par[384 + tid] = ln_b[layer*H + tid];
    }

    int rowA = tid >> 2, segA = tid & 3;
    uint32_t dstA = AR + (uint32_t)rowA*80 + (uint32_t)segA*16;
    const __nv_bfloat16* srcAh = g_yh + (bt0+rowA)*H + segA*8;
    const __nv_bfloat16* srcAl = g_yl + (bt0+rowA)*H + segA*8;

    uint32_t dstB[6];
    #pragma unroll
    for(int m=0;m<6;m++){
        int id = tid + m*256;
        int d = id / 768;
        int rem = id - d*768;
        int o = rem >> 2, s = rem & 3;
        dstB[m] = BR + (uint32_t)d*BSTG_D + (uint32_t)o*80 + (uint32_t)s*16;
    }
    const uint4* wrp = (const uint4*)g_wr + (size_t)layer*9216 + tid;

#define ISSUE_CHUNK(cc, st) do { \
    uint32_t _as = sbase + (st)*ASTG; \
    CP16(_as + dstA,          srcAh + (cc)*32); \
    CP16(_as + dstA + ASTG_D, srcAl + (cc)*32); \
    uint32_t _bs = sbase + (st)*BSTG; \
    const uint4* _w = wrp + (cc)*1536; \
    _Pragma("unroll") \
    for(int m=0;m<6;m++) CP16(_bs + dstB[m], _w + m*256); \
    CP_COMMIT; \
} while(0)

    ISSUE_CHUNK(0, 0);
    ISSUE_CHUNK(1, 1);

    int g2 = lane >> 3, lr = lane & 7;
    uint32_t aOff[2];
    #pragma unroll
    for(int mt=0;mt<2;mt++)
        aOff[mt] = AR + (uint32_t)(wm*32 + mt*16 + (g2&1)*8 + lr)*80 + (uint32_t)(g2>>1)*16;
    uint32_t bOff[3];
    #pragma unroll
    for(int i=0;i<3;i++)
        bOff[i] = BR + (uint32_t)(wn*48 + i*16 + (g2>>1)*8 + lr)*80 + (uint32_t)(g2&1)*16;

    float acc[2][6][4];
    #pragma unroll
    for(int mt=0;mt<2;mt++)
        #pragma unroll
        for(int nt=0;nt<6;nt++)
            #pragma unroll
            for(int r=0;r<4;r++) acc[mt][nt][r] = 0.f;

    #pragma unroll 1
    for(int c=0;c<6;c++){
        if(c<5){ CP_WAIT1; } else { CP_WAIT0; }
        __syncthreads();
        int st = c & 1;
        uint32_t aH = sbase + st*ASTG;
        uint32_t bH = sbase + st*BSTG;
        #pragma unroll
        for(int ks=0;ks<2;ks++){
            uint32_t kOf = (uint32_t)ks*32;
            uint32_t ah[2][4], al[2][4], bb[3][4];
            LDSM4(ah[0], aH + aOff[0] + kOf);
            LDSM4(ah[1], aH + aOff[1] + kOf);
            LDSM4(al[0], aH + aOff[0] + ASTG_D + kOf);
            LDSM4(al[1], aH + aOff[1] + ASTG_D + kOf);
            #pragma unroll
            for(int i=0;i<3;i++) LDSM4(bb[i], bH + bOff[i] + kOf);
            // pass 1: Ah*Bh — each acc written exactly once
            #pragma unroll
            for(int mt=0;mt<2;mt++)
                #pragma unroll
                for(int i=0;i<3;i++){
                    MMA16816(acc[mt][2*i],   ah[mt], bb[i][0], bb[i][1]);
                    MMA16816(acc[mt][2*i+1], ah[mt], bb[i][2], bb[i][3]);
                }
            // pass 2: Al*Bh — distance 12 from pass 1 on same acc
            #pragma unroll
            for(int mt=0;mt<2;mt++)
                #pragma unroll
                for(int i=0;i<3;i++){
                    MMA16816(acc[mt][2*i],   al[mt], bb[i][0], bb[i][1]);
                    MMA16816(acc[mt][2*i+1], al[mt], bb[i][2], bb[i][3]);
                }
            // bh dead -> bl recolors onto same registers
            #pragma unroll
            for(int i=0;i<3;i++) LDSM4(bb[i], bH + bOff[i] + BSTG_D + kOf);
            // pass 3: Ah*Bl — distance 12 from pass 2 on same acc
            #pragma unroll
            for(int mt=0;mt<2;mt++)
                #pragma unroll
                for(int i=0;i<3;i++){
                    MMA16816(acc[mt][2*i],   ah[mt], bb[i][0], bb[i][1]);
                    MMA16816(acc[mt][2*i+1], ah[mt], bb[i][2], bb[i][3]);
                }
        }
        __syncthreads();
        if(c<4) ISSUE_CHUNK(c+2, st);
    }

    // ---------------- epilogue: bias + LN + gelu + residual ----------------
    float* red1 = (float*)(smem + AR);
    float* red2 = red1 + 256;
    float* musm = red1 + 512;
    float* rssm = red1 + 576;

    float s1[2][2] = {{0.f,0.f},{0.f,0.f}};
    float s2[2][2] = {{0.f,0.f},{0.f,0.f}};
    #pragma unroll
    for(int mt=0;mt<2;mt++)
        #pragma unroll
        for(int nt=0;nt<6;nt++){
            int col = wn*48 + nt*8 + qi*2;
            float b0 = par[col], b1 = par[col+1];
            acc[mt][nt][0] += b0; acc[mt][nt][1] += b1;
            acc[mt][nt][2] += b0; acc[mt][nt][3] += b1;
            #pragma unroll
            for(int h=0;h<2;h++){
                float v0 = acc[mt][nt][h*2], v1 = acc[mt][nt][h*2+1];
                s1[mt][h] += v0 + v1;
                s2[mt][h] += v0*v0 + v1*v1;
            }
        }
    #pragma unroll
    for(int mt=0;mt<2;mt++)
        #pragma unroll
        for(int h=0;h<2;h++){
            float a = s1[mt][h], b2 = s2[mt][h];
            a  += __shfl_xor_sync(0xffffffffu, a, 1);
            a  += __shfl_xor_sync(0xffffffffu, a, 2);
            b2 += __shfl_xor_sync(0xffffffffu, b2, 1);
            b2 += __shfl_xor_sync(0xffffffffu, b2, 2);
            if(qi==0){
                int row = wm*32 + mt*16 + h*8 + q;
                red1[wn*64 + row] = a;
                red2[wn*64 + row] = b2;
            }
        }
    __syncthreads();
    if(tid < 64){
        float t1 = red1[tid] + red1[64+tid] + red1[128+tid] + red1[192+tid];
        float t2 = red2[tid] + red2[64+tid] + red2[128+tid] + red2[192+tid];
        float mu = t1*(1.0f/H);
        musm[tid] = mu;
        rssm[tid] = rsqrtf(t2*(1.0f/H) - mu*mu + 1e-5f);
    }
    __syncthreads();

    const float* lg = par + 192;
    const float* lb = par + 384;
    #pragma unroll
    for(int mt=0;mt<2;mt++)
        #pragma unroll
        for(int h=0;h<2;h++){
            int row = wm*32 + mt*16 + h*8 + q;
            float mu = musm[row], rs = rssm[row];
            float* xrow = g_x + (bt0+row)*H;
            __nv_bfloat16* yh = g_yh + (bt0+row)*H;
            __nv_bfloat16* yl = g_yl + (bt0+row)*H;
            #pragma unroll
            for(int nt=0;nt<6;nt++){
                int col = wn*48 + nt*8 + qi*2;
                float v0 = acc[mt][nt][h*2], v1 = acc[mt][nt][h*2+1];
                float2 res = *(float2*)(xrow + col);
                float o0 = gelu_exact((v0-mu)*rs*lg[col]   + lb[col])   + res.x;
                float o1 = gelu_exact((v1-mu)*rs*lg[col+1] + lb[col+1]) + res.y;
                *(float2*)(xrow + col) = make_float2(o0, o1);
                if(last){
                    __nv_bfloat16 h0 = __float2bfloat16(o0);
                    __nv_bfloat16 h1 = __float2bfloat16(o1);
                    __nv_bfloat16 l0 = __float2bfloat16(o0 - __bfloat162float(h0));
                    __nv_bfloat16 l1 = __float2bfloat16(o1 - __bfloat162float(h1));
                    __nv_bfloat162 ph = __halves2bfloat162(h0,h1);
                    __nv_bfloat162 pl = __halves2bfloat162(l0,l1);
                    *(__nv_bfloat162*)(yh + col) = ph;
                    *(__nv_bfloat162*)(yl + col) = pl;
                }
            }
        }
}

// ---------------------------------------------------------------------------
// spline: P = x_final . proj_w^T via split-bf16 mma, then RQ spline + logdet
#define SP_PWHI 0
#define SP_PWLO 12800
#define SP_ABUF 25600
#define SP_P    25600
#define SPLINE_SMEM_BYTES (25600 + 2*40960)

__global__ void __launch_bounds__(256) k_spline(
    const float* __restrict__ x, const float* __restrict__ xmask,
    const float* __restrict__ proj_b,
    float* __restrict__ out)
{
    extern __shared__ char smem[];
    uint32_t sbase = smem_u32(smem);
    int tid = threadIdx.x;
    int wid = tid >> 5, lane = tid & 31;
    int q = lane >> 2, qi = lane & 3;
    long long bt0 = (long long)blockIdx.x * 256;

    {
        const uint4* src = (const uint4*)g_pw;
        uint4* dst = (uint4*)smem;
        #pragma unroll
        for(int i=tid;i<1600;i+=256) dst[i] = src[i];
    }

    int rows[4], segs[4];
    #pragma unroll
    for(int m=0;m<4;m++){
        int id = tid + m*256;
        rows[m] = id >> 2; segs[m] = id & 3;
    }

#define SP_ISSUE(cc, st) do { \
    uint32_t _ah = sbase + SP_ABUF + (st)*40960; \
    uint32_t _al = _ah + 20480; \
    int _k = (cc)*32; \
    _Pragma("unroll") \
    for(int m=0;m<4;m++){ \
        uint32_t d = (uint32_t)rows[m]*80 + (uint32_t)segs[m]*16; \
        CP16(_ah + d, g_yh + (bt0+rows[m])*H + segs[m]*8 + _k); \
        CP16(_al + d, g_yl + (bt0+rows[m])*H + segs[m]*8 + _k); \
    } \
    CP_COMMIT; \
} while(0)

    SP_ISSUE(0, 0);
    SP_ISSUE(1, 1);

    int g2 = lane >> 3, lr = lane & 7;
    uint32_t aOff[2];
    #pragma unroll
    for(int mt=0;mt<2;mt++)
        aOff[mt] = (uint32_t)(wid*32 + mt*16 + (g2&1)*8 + lr)*80 + (uint32_t)(g2>>1)*16;
    uint32_t bOff[2];
    #pragma unroll
    for(int i=0;i<2;i++)
        bOff[i] = (uint32_t)(i*16 + (g2>>1)*8 + lr)*400 + (uint32_t)(g2&1)*16;

    float acc[2][4][4];
    #pragma unroll
    for(int mt=0;mt<2;mt++)
        #pragma unroll
        for(int nt=0;nt<4;nt++)
            #pragma unroll
            for(int r=0;r<4;r++) acc[mt][nt][r]=0.f;

    #pragma unroll 1
    for(int c=0;c<6;c++){
        if(c<5){ CP_WAIT1; } else { CP_WAIT0; }
        __syncthreads();
        uint32_t abufH = sbase + SP_ABUF + (c&1)*40960;
        uint32_t abufL = abufH + 20480;
        #pragma unroll
        for(int ks=0;ks<2;ks++){
            uint32_t kA = ks*32;
            uint32_t kB = (uint32_t)c*64 + ks*32;
            uint32_t ah[2][4], al[2][4], bb[2][4];
            LDSM4(ah[0], abufH + aOff[0] + kA);
            LDSM4(ah[1], abufH + aOff[1] + kA);
            LDSM4(al[0], abufL + aOff[0] + kA);
            LDSM4(al[1], abufL + aOff[1] + kA);
            LDSM4(bb[0], sbase + SP_PWHI + bOff[0] + kB);
            LDSM4(bb[1], sbase + SP_PWHI + bOff[1] + kB);
            // pass 1: Ah*Bh
            #pragma unroll
            for(int mt=0;mt<2;mt++)
                #pragma unroll
                for(int i=0;i<2;i++){
                    MMA16816(acc[mt][2*i],   ah[mt], bb[i][0], bb[i][1]);
                    MMA16816(acc[mt][2*i+1], ah[mt], bb[i][2], bb[i][3]);
                }
            // pass 2: Al*Bh
            #pragma unroll
            for(int mt=0;mt<2;mt++)
                #pragma unroll
                for(int i=0;i<2;i++){
                    MMA16816(acc[mt][2*i],   al[mt], bb[i][0], bb[i][1]);
                    MMA16816(acc[mt][2*i+1], al[mt], bb[i][2], bb[i][3]);
                }
            LDSM4(bb[0], sbase + SP_PWLO + bOff[0] + kB);
            LDSM4(bb[1], sbase + SP_PWLO + bOff[1] + kB);
            // pass 3: Ah*Bl
            #pragma unroll
            for(int mt=0;mt<2;mt++)
                #pragma unroll
                for(int i=0;i<2;i++){
                    MMA16816(acc[mt][2*i],   ah[mt], bb[i][0], bb[i][1]);
                    MMA16816(acc[mt][2*i+1], ah[mt], bb[i][2], bb[i][3]);
                }
        }
        __syncthreads();
        if(c<4) SP_ISSUE(c+2, c&1);
    }

    float* Psm = (float*)(smem + SP_P);
    #pragma unroll
    for(int mt=0;mt<2;mt++)
        #pragma unroll
        for(int h=0;h<2;h++){
            int row = wid*32 + mt*16 + h*8 + q;
            #pragma unroll
            for(int nt=0;nt<4;nt++){
                int col = nt*8 + qi*2;
                Psm[row*33 + col]   = acc[mt][nt][h*2];
                Psm[row*33 + col+1] = acc[mt][nt][h*2+1];
            }
        }
    __syncthreads();

    int b = (int)(bt0 >> 13);
    int t = (int)(bt0 & (T-1)) + tid;
    float mask = xmask[(long long)b*T + t];

    float p[NJ];
    #pragma unroll
    for(int j=0;j<NJ;j++) p[j] = (Psm[tid*33 + j] + __ldg(proj_b + j)) * mask;

    const float inv_dn = 0.07216878364870323f;   // 1/sqrt(192)

    float cwv[BINS+1], wsv[BINS];
    {
        float m = -1e30f;
        #pragma unroll
        for(int j=0;j<BINS;j++) m = fmaxf(m, p[j]);
        float e[BINS]; float ssum = 0.f;
        #pragma unroll
        for(int j=0;j<BINS;j++){ e[j] = expf((p[j]-m)*inv_dn); ssum += e[j]; }
        float inv = 1.0f/ssum;
        float cum = 0.f;
        cwv[0] = -TAILV;
        #pragma unroll
        for(int j=0;j<BINS;j++){
            float wj = 1e-3f + 0.99f*e[j]*inv;
            cum += wj;
            cwv[j+1] = 2.0f*TAILV*cum - TAILV;
        }
        cwv[BINS] = TAILV;
        #pragma unroll
        for(int j=0;j<BINS;j++) wsv[j] = cwv[j+1]-cwv[j];
    }
    float chv[BINS+1], hsv[BINS];
    {
        float m = -1e30f;
        #pragma unroll
        for(int j=0;j<BINS;j++) m = fmaxf(m, p[BINS+j]);
        float e[BINS]; float ssum = 0.f;
        #pragma unroll
        for(int j=0;j<BINS;j++){ e[j] = expf((p[BINS+j]-m)*inv_dn); ssum += e[j]; }
        float inv = 1.0f/ssum;
        float cum = 0.f;
        chv[0] = -TAILV;
        #pragma unroll
        for(int j=0;j<BINS;j++){
            float hj = 1e-3f + 0.99f*e[j]*inv;
            cum += hj;
            chv[j+1] = 2.0f*TAILV*cum - TAILV;
        }
        chv[BINS] = TAILV;
        #pragma unroll
        for(int j=0;j<BINS;j++) hsv[j] = chv[j+1]-chv[j];
    }
    float derv[BINS+1];
    derv[0] = 1.0f; derv[BINS] = 1.0f;
    #pragma unroll
    for(int k=1;k<BINS;k++){
        float u = p[2*BINS + k - 1];
        float sp = (u > 20.f) ? u : log1pf(expf(u));
        derv[k] = 1e-3f + sp;
    }

    float xbv = x[((long long)b*2+1)*T + t];
    bool inside = (xbv >= -TAILV) && (xbv <= TAILV);
    float xc = fminf(fmaxf(xbv, -TAILV), TAILV);
    int idx = 0;
    #pragma unroll
    for(int j=0;j<BINS;j++) idx += (xc >= cwv[j]) ? 1 : 0;
    idx -= 1;
    idx = max(0, min(BINS-1, idx));

    float icw=0.f, ibw=1.f, ich=0.f, ih=1.f, dk=1.f, dk1=1.f;
    #pragma unroll
    for(int j=0;j<BINS;j++){
        bool sel = (idx==j);
        icw = sel ? cwv[j]   : icw;
        ibw = sel ? wsv[j]   : ibw;
        ich = sel ? chv[j]   : ich;
        ih  = sel ? hsv[j]   : ih;
        dk  = sel ? derv[j]  : dk;
        dk1 = sel ? derv[j+1]: dk1;
    }

    float idl = ih/ibw;
    float th  = (xc - icw)/ibw;
    float t1m = th*(1.0f - th);
    float num = ih*(idl*th*th + dk*t1m);
    float den = idl + (dk + dk1 - 2.0f*idl)*t1m;
    float outv = ich + num/den;
    float omt = 1.0f - th;
    float dnum = idl*idl*(dk1*th*th + 2.0f*idl*t1m + dk*omt*omt);
    float lad = logf(dnum) - 2.0f*logf(den);

    float xb2 = inside ? outv : xbv;
    lad = inside ? lad : 0.0f;

    float xav = x[((long long)b*2)*T + t];
    out[(long long)b*2*T + t]     = xav*mask;
    out[(long long)b*2*T + T + t] = xb2*mask;

    float lv = lad*mask;
    #pragma unroll
    for(int o=16;o>0;o>>=1) lv += __shfl_xor_sync(0xffffffffu, lv, o);
    static __shared__ float red8[8];
    if(lane == 0) red8[wid] = lv;
    __syncthreads();
    if(tid == 0){
        float acc8 = red8[0]+red8[1]+red8[2]+red8[3]+red8[4]+red8[5]+red8[6]+red8[7];
        atomicAdd(out + (long long)B*2*T + b, acc8);
    }
}

// ---------------------------------------------------------------------------
extern "C" void kernel_launch(void* const* d_in, const int* in_sizes, int n_in,
                              void* d_out, int out_size)
{
    const float* x      = (const float*)d_in[0];
    const float* xmask  = (const float*)d_in[1];
    const float* in_w   = (const float*)d_in[2];
    const float* in_b   = (const float*)d_in[3];
    const float* dw_w   = (const float*)d_in[4];
    const float* dw_b   = (const float*)d_in[5];
    const float* ln1_g  = (const float*)d_in[6];
    const float* ln1_b  = (const float*)d_in[7];
    const float* pw_w   = (const float*)d_in[8];
    const float* pw_b   = (const float*)d_in[9];
    const float* ln2_g  = (const float*)d_in[10];
    const float* ln2_b  = (const float*)d_in[11];
    const float* proj_w = (const float*)d_in[12];
    const float* proj_b = (const float*)d_in[13];
    float* out = (float*)d_out;

    cudaFuncSetAttribute(k_gemm_mma, cudaFuncAttributeMaxDynamicSharedMemorySize, GEMM_SMEM_BYTES);
    cudaFuncSetAttribute(k_spline,   cudaFuncAttributeMaxDynamicSharedMemorySize, SPLINE_SMEM_BYTES);

    k_zero<<<1, 32>>>(out);
    k_prep<<<(3*H*H + 255)/256, 256>>>(pw_w, proj_w, dw_w);
    int dil = 1;
    for(int L=0; L<3; L++){
        k_conv<<<BT/32, 256>>>(L, dil, x, in_w, in_b, xmask, dw_b, ln1_g, ln1_b);
        k_gemm_mma<<<BT/64, 256, GEMM_SMEM_BYTES>>>(L, (L==2)?1:0, pw_b, ln2_g, ln2_b);
        dil *= 3;
    }
    k_spline<<<BT/256, 256, SPLINE_SMEM_BYTES>>>(x, xmask, proj_b, out);
}

// round 8
// speedup vs baseline: 1.1209x; 1.1209x over previous
#include <cuda_runtime.h>
#include <cuda_bf16.h>
#include <math.h>
#include <stdint.h>

#define B 32
#define T 8192
#define H 192
#define BT (B*T)
#define BINS 10
#define TAILV 5.0f
#define NJ 29

// residual stream (f32) and bf16 hi/lo stream, layout [b][t][c]
__device__ float g_x[(size_t)BT*H];
__device__ __align__(16) __nv_bfloat16 g_yh[(size_t)BT*H];
__device__ __align__(16) __nv_bfloat16 g_yl[(size_t)BT*H];
// chunk-ordered pw weight image: [layer][chunk(6)][dtype(2)][o=192][seg(4)][8 bf16]
__device__ __align__(16) __nv_bfloat16 g_wr[3*6*2*192*32];
// padded proj weight image: [hi/lo][32][pad 200] bf16
__device__ __align__(16) __nv_bfloat16 g_pw[2*32*200];
// transposed depthwise weights: [layer][tap][c]
__device__ float g_dwt[3*3*192];

__device__ __forceinline__ float gelu_exact(float v){
    return 0.5f*v*(1.0f+erff(v*0.70710678118654752f));
}

__device__ __forceinline__ uint32_t smem_u32(const void* p){
    uint32_t a;
    asm("{ .reg .u64 t; cvta.to.shared.u64 t, %1; cvt.u32.u64 %0, t; }" : "=r"(a) : "l"(p));
    return a;
}

#define LDSM4(r, addr) \
    asm volatile("ldmatrix.sync.aligned.m8n8.x4.shared.b16 {%0,%1,%2,%3}, [%4];" \
        : "=r"((r)[0]),"=r"((r)[1]),"=r"((r)[2]),"=r"((r)[3]) : "r"(addr))

#define MMA16816(d, a, b0, b1) \
    asm volatile("mma.sync.aligned.m16n8k16.row.col.f32.bf16.bf16.f32 " \
        "{%0,%1,%2,%3},{%4,%5,%6,%7},{%8,%9},{%0,%1,%2,%3};" \
        : "+f"((d)[0]),"+f"((d)[1]),"+f"((d)[2]),"+f"((d)[3]) \
        : "r"((a)[0]),"r"((a)[1]),"r"((a)[2]),"r"((a)[3]), "r"(b0),"r"(b1))

#define CP16(dst, src) \
    asm volatile("cp.async.cg.shared.global [%0], [%1], 16;" :: "r"(dst), "l"(src))
#define CP_COMMIT asm volatile("cp.async.commit_group;" ::: "memory")
#define CP_WAIT1  asm volatile("cp.async.wait_group 1;" ::: "memory")
#define CP_WAIT0  asm volatile("cp.async.wait_group 0;" ::: "memory")

// ---------------------------------------------------------------------------
__global__ void k_zero(float* __restrict__ out){
    out[(long long)B*2*T + threadIdx.x] = 0.0f;
}

// prep: pw chunk-ordered split image, proj split image, dw transpose
__global__ void k_prep(const float* __restrict__ pw_w,
                       const float* __restrict__ proj_w,
                       const float* __restrict__ dw_w)
{
    int i = blockIdx.x*256 + threadIdx.x;
    if (i < 3*H*H){
        int L = i / (H*H);
        int r = i - L*(H*H);
        int o = r / H, k = r - o*H;
        float w = pw_w[i];
        __nv_bfloat16 hb = __float2bfloat16(w);
        __nv_bfloat16 lb = __float2bfloat16(w - __bfloat162float(hb));
        int c = k >> 5;
        int s = (k >> 3) & 3;
        int j = k & 7;
        size_t base = ((size_t)(L*6 + c)*1536 + (size_t)o*4 + s)*8 + j;
        g_wr[base]          = hb;
        g_wr[base + 6144]   = lb;
    }
    if (i < 2*32*200){
        int p = i / 6400;
        int rem = i - p*6400;
        int r = rem / 200, c = rem - r*200;
        float w = (r < NJ && c < H) ? proj_w[r*H + c] : 0.0f;
        __nv_bfloat16 hb = __float2bfloat16(w);
        __nv_bfloat16 lb = __float2bfloat16(w - __bfloat162float(hb));
        g_pw[i] = p ? lb : hb;
    }
    if (i < 3*3*H){
        int L = i / (3*H);
        int rem = i - L*(3*H);
        int c = rem / 3, k = rem - c*3;
        g_dwt[L*(3*H) + k*H + c] = dw_w[i];
    }
}

// ---------------------------------------------------------------------------
// depthwise dilated conv (K=3) + LN + exact gelu -> bf16 hi/lo.
__global__ void __launch_bounds__(256) k_conv(int layer, int dil,
    const float* __restrict__ x,
    const float* __restrict__ in_w, const float* __restrict__ in_b,
    const float* __restrict__ xmask,
    const float* __restrict__ dw_b,
    const float* __restrict__ ln_g, const float* __restrict__ ln_b)
{
    int wid = threadIdx.x >> 5, lane = threadIdx.x & 31;
    long long g0 = (long long)blockIdx.x*32 + wid*4;
    int b = (int)(g0 >> 13);
    int t0 = (int)(g0 & (T-1));
    int c0 = lane*6;
    bool first = (layer == 0);

    float w0[6], w1[6], w2[6], bbv[6], ggv[6], gbv[6];
    {
        const float* wt = g_dwt + layer*(3*H);
        #pragma unroll
        for(int p=0;p<3;p++){
            float2 a = *(const float2*)(wt + c0 + p*2);
            w0[p*2]=a.x; w0[p*2+1]=a.y;
            float2 bq = *(const float2*)(wt + H + c0 + p*2);
            w1[p*2]=bq.x; w1[p*2+1]=bq.y;
            float2 cq = *(const float2*)(wt + 2*H + c0 + p*2);
            w2[p*2]=cq.x; w2[p*2+1]=cq.y;
            float2 d = *(const float2*)(dw_b + layer*H + c0 + p*2);
            bbv[p*2]=d.x; bbv[p*2+1]=d.y;
            float2 e = *(const float2*)(ln_g + layer*H + c0 + p*2);
            ggv[p*2]=e.x; ggv[p*2+1]=e.y;
            float2 f = *(const float2*)(ln_b + layer*H + c0 + p*2);
            gbv[p*2]=f.x; gbv[p*2+1]=f.y;
        }
    }
    float iw[6], ib[6];
    if(first){
        #pragma unroll
        for(int p=0;p<3;p++){
            float2 a = *(const float2*)(in_w + c0 + p*2);
            iw[p*2]=a.x; iw[p*2+1]=a.y;
            float2 bq = *(const float2*)(in_b + c0 + p*2);
            ib[p*2]=bq.x; ib[p*2+1]=bq.y;
        }
    }
    const float* mrow = xmask + (long long)b*T;
    const float* xrowa = x + ((long long)b*2)*T;

    #pragma unroll
    for(int tt=0;tt<4;tt++){
        long long row = g0 + tt;
        int t = t0 + tt;
        int tm = t - dil, tp = t + dil;
        bool hm = (tm >= 0), hp = (tp < T);
        float mm = hm ? mrow[tm] : 0.f;
        float m0 = mrow[t];
        float mp = hp ? mrow[tp] : 0.f;

        float xm[6], xz[6], xp[6];
        if(first){
            float xam = hm ? xrowa[tm] : 0.f;
            float xa0 = xrowa[t];
            float xap = hp ? xrowa[tp] : 0.f;
            #pragma unroll
            for(int k=0;k<6;k++){
                xm[k] = iw[k]*xam + ib[k];
                xz[k] = iw[k]*xa0 + ib[k];
                xp[k] = iw[k]*xap + ib[k];
            }
            float* gx = g_x + row*H + c0;
            #pragma unroll
            for(int p=0;p<3;p++)
                *(float2*)(gx + p*2) = make_float2(xz[p*2], xz[p*2+1]);
        } else {
            const float* base = g_x + row*H + c0;
            #pragma unroll
            for(int p=0;p<3;p++){
                float2 a = *(const float2*)(base + p*2);
                xz[p*2]=a.x; xz[p*2+1]=a.y;
            }
            if(hm){
                const float* bmp = base - (long long)dil*H;
                #pragma unroll
                for(int p=0;p<3;p++){
                    float2 a = *(const float2*)(bmp + p*2);
                    xm[p*2]=a.x; xm[p*2+1]=a.y;
                }
            } else {
                #pragma unroll
                for(int k=0;k<6;k++) xm[k]=0.f;
            }
            if(hp){
                const float* bpp = base + (long long)dil*H;
                #pragma unroll
                for(int p=0;p<3;p++){
                    float2 a = *(const float2*)(bpp + p*2);
                    xp[p*2]=a.x; xp[p*2+1]=a.y;
                }
            } else {
                #pragma unroll
                for(int k=0;k<6;k++) xp[k]=0.f;
            }
        }

        float v[6];
        float s=0.f, sq=0.f;
        #pragma unroll
        for(int k=0;k<6;k++){
            float r = w0[k]*(xm[k]*mm) + w1[k]*(xz[k]*m0) + w2[k]*(xp[k]*mp) + bbv[k];
            v[k]=r; s+=r; sq+=r*r;
        }
        #pragma unroll
        for(int o=16;o>0;o>>=1){
            s  += __shfl_xor_sync(0xffffffffu, s,  o);
            sq += __shfl_xor_sync(0xffffffffu, sq, o);
        }
        float mu = s*(1.0f/H);
        float rs = rsqrtf(sq*(1.0f/H) - mu*mu + 1e-5f);

        uint32_t hw[3], lw[3];
        #pragma unroll
        for(int p=0;p<3;p++){
            float y0 = gelu_exact((v[p*2]  -mu)*rs*ggv[p*2]   + gbv[p*2]);
            float y1 = gelu_exact((v[p*2+1]-mu)*rs*ggv[p*2+1] + gbv[p*2+1]);
            __nv_bfloat16 h0 = __float2bfloat16(y0);
            __nv_bfloat16 h1 = __float2bfloat16(y1);
            __nv_bfloat16 l0 = __float2bfloat16(y0 - __bfloat162float(h0));
            __nv_bfloat16 l1 = __float2bfloat16(y1 - __bfloat162float(h1));
            __nv_bfloat162 ph = __halves2bfloat162(h0,h1);
            __nv_bfloat162 pl = __halves2bfloat162(l0,l1);
            hw[p] = *(uint32_t*)&ph;
            lw[p] = *(uint32_t*)&pl;
        }
        uint32_t* oh = (uint32_t*)(g_yh + row*H + c0);
        uint32_t* ol = (uint32_t*)(g_yl + row*H + c0);
        oh[0]=hw[0]; oh[1]=hw[1]; oh[2]=hw[2];
        ol[0]=lw[0]; ol[1]=lw[1]; ol[2]=lw[2];
    }
}

// ---------------------------------------------------------------------------
// warp-MMA GEMM: D[t(64), o(192)] = Y . W^T, split-bf16.
// 3-stage cp.async ring, ONE barrier per chunk, XOR-swizzled 64B rows,
// ks-level operand prefetch. 256 threads (2Mx4N warps), 2 CTAs/SM.
// swizzle: off(row,seg) = row*64 + ((seg ^ ((row>>1)&3))<<4)
#define STG_SZ  32768
#define STG_AH  0
#define STG_AL  4096
#define STG_BH  8192
#define STG_BL  20480
#define PAR_OFF (3*STG_SZ)
#define GEMM_SMEM_BYTES (PAR_OFF + 2304)

__global__ void __launch_bounds__(256,2) k_gemm_mma(int layer, int last,
    const float* __restrict__ pw_b,
    const float* __restrict__ ln_g, const float* __restrict__ ln_b)
{
    extern __shared__ char smem[];
    uint32_t sbase = smem_u32(smem);
    int tid = threadIdx.x;
    int wid = tid >> 5, lane = tid & 31;
    int wm = wid & 1, wn = wid >> 1;        // 2 warps in M, 4 in N
    int q = lane >> 2, qi = lane & 3;
    long long bt0 = (long long)blockIdx.x * 64;

    float* par = (float*)(smem + PAR_OFF);
    if(tid < 192){
        par[tid]       = pw_b[layer*H + tid];
        par[192 + tid] = ln_g[layer*H + tid];
        par[384 + tid] = ln_b[layer*H + tid];
    }

    // A loader: one (row, seg) per thread per dtype
    int rowA = tid >> 2, segA = tid & 3;
    uint32_t dstA = (uint32_t)rowA*64 + (uint32_t)((segA ^ ((rowA>>1)&3)) << 4);
    const __nv_bfloat16* srcAh = g_yh + (bt0+rowA)*H + segA*8;
    const __nv_bfloat16* srcAl = g_yl + (bt0+rowA)*H + segA*8;

    // B loader: 1536 segs per chunk, 6 per thread
    uint32_t dstB[6];
    #pragma unroll
    for(int m=0;m<6;m++){
        int id = tid + m*256;
        int d = id / 768;
        int rem = id - d*768;
        int o = rem >> 2, s = rem & 3;
        dstB[m] = STG_BH + (uint32_t)d*12288 + (uint32_t)o*64
                + (uint32_t)((s ^ ((o>>1)&3)) << 4);
    }
    const uint4* wrp = (const uint4*)g_wr + (size_t)layer*9216 + tid;

#define ISSUE_CHUNK(cc, st) do { \
    uint32_t _s = sbase + (st)*STG_SZ; \
    CP16(_s + STG_AH + dstA, srcAh + (cc)*32); \
    CP16(_s + STG_AL + dstA, srcAl + (cc)*32); \
    const uint4* _w = wrp + (cc)*1536; \
    _Pragma("unroll") \
    for(int m=0;m<6;m++) CP16(_s + dstB[m], _w + m*256); \
    CP_COMMIT; \
} while(0)

    ISSUE_CHUNK(0, 0);
    ISSUE_CHUNK(1, 1);

    // per-thread ldmatrix offsets (swizzled), per ks
    int g2 = lane >> 3, lr = lane & 7;
    uint32_t aOffs[2][2], bOffs[2][3];
    #pragma unroll
    for(int mt=0;mt<2;mt++){
        int row = wm*32 + mt*16 + (g2&1)*8 + lr;
        int xr = (row>>1)&3;
        #pragma unroll
        for(int ks=0;ks<2;ks++){
            int seg = ks*2 + (g2>>1);
            aOffs[ks][mt] = (uint32_t)row*64 + (uint32_t)(((seg ^ xr)&3) << 4);
        }
    }
    #pragma unroll
    for(int i=0;i<3;i++){
        int row = wn*48 + i*16 + (g2>>1)*8 + lr;
        int xr = (row>>1)&3;
        #pragma unroll
        for(int ks=0;ks<2;ks++){
            int seg = ks*2 + (g2&1);
            bOffs[ks][i] = (uint32_t)row*64 + (uint32_t)(((seg ^ xr)&3) << 4);
        }
    }

    float acc[2][6][4];
    #pragma unroll
    for(int mt=0;mt<2;mt++)
        #pragma unroll
        for(int nt=0;nt<6;nt++)
            #pragma unroll
            for(int r=0;r<4;r++) acc[mt][nt][r] = 0.f;

#define PASS(AH, BB) \
    _Pragma("unroll") \
    for(int mt=0;mt<2;mt++){ \
        _Pragma("unroll") \
        for(int i=0;i<3;i++){ \
            MMA16816(acc[mt][2*i],   AH[mt], BB[i][0], BB[i][1]); \
            MMA16816(acc[mt][2*i+1], AH[mt], BB[i][2], BB[i][3]); \
        } \
    }

    #pragma unroll 1
    for(int c=0;c<6;c++){
        if(c<5){ CP_WAIT1; } else { CP_WAIT0; }
        __syncthreads();
        if(c<4) ISSUE_CHUNK(c+2, (c+2)%3);
        uint32_t sb = sbase + (uint32_t)(c%3)*STG_SZ;

        uint32_t ah0[2][4], al0[2][4], ah1[2][4], al1[2][4], bb[3][4];
        // ks=0 A operands + B-hi, then prefetch ks=1 A operands
        LDSM4(ah0[0], sb + STG_AH + aOffs[0][0]);
        LDSM4(ah0[1], sb + STG_AH + aOffs[0][1]);
        LDSM4(al0[0], sb + STG_AL + aOffs[0][0]);
        LDSM4(al0[1], sb + STG_AL + aOffs[0][1]);
        #pragma unroll
        for(int i=0;i<3;i++) LDSM4(bb[i], sb + STG_BH + bOffs[0][i]);
        LDSM4(ah1[0], sb + STG_AH + aOffs[1][0]);
        LDSM4(ah1[1], sb + STG_AH + aOffs[1][1]);
        LDSM4(al1[0], sb + STG_AL + aOffs[1][0]);
        LDSM4(al1[1], sb + STG_AL + aOffs[1][1]);

        PASS(ah0, bb)                                   // Ah*Bh  ks0
        PASS(al0, bb)                                   // Al*Bh  ks0
        #pragma unroll
        for(int i=0;i<3;i++) LDSM4(bb[i], sb + STG_BL + bOffs[0][i]);
        PASS(ah0, bb)                                   // Ah*Bl  ks0
        #pragma unroll
        for(int i=0;i<3;i++) LDSM4(bb[i], sb + STG_BH + bOffs[1][i]);
        PASS(ah1, bb)                                   // Ah*Bh  ks1
        PASS(al1, bb)                                   // Al*Bh  ks1
        #pragma unroll
        for(int i=0;i<3;i++) LDSM4(bb[i], sb + STG_BL + bOffs[1][i]);
        PASS(ah1, bb)                                   // Ah*Bl  ks1
    }
#undef PASS

    // ---------------- epilogue: bias + LN + gelu + residual ----------------
    // overlay reduction arrays on stage 0 (dead: all warps past chunk-4 reads)
    float* red1 = (float*)smem;
    float* red2 = red1 + 256;
    float* musm = red1 + 512;
    float* rssm = red1 + 576;

    float s1[2][2] = {{0.f,0.f},{0.f,0.f}};
    float s2[2][2] = {{0.f,0.f},{0.f,0.f}};
    #pragma unroll
    for(int mt=0;mt<2;mt++)
        #pragma unroll
        for(int nt=0;nt<6;nt++){
            int col = wn*48 + nt*8 + qi*2;
            float b0 = par[col], b1 = par[col+1];
            acc[mt][nt][0] += b0; acc[mt][nt][1] += b1;
            acc[mt][nt][2] += b0; acc[mt][nt][3] += b1;
            #pragma unroll
            for(int h=0;h<2;h++){
                float v0 = acc[mt][nt][h*2], v1 = acc[mt][nt][h*2+1];
                s1[mt][h] += v0 + v1;
                s2[mt][h] += v0*v0 + v1*v1;
            }
        }
    __syncthreads();   // all warps done with mainloop stages before overlay
    #pragma unroll
    for(int mt=0;mt<2;mt++)
        #pragma unroll
        for(int h=0;h<2;h++){
            float a = s1[mt][h], b2 = s2[mt][h];
            a  += __shfl_xor_sync(0xffffffffu, a, 1);
            a  += __shfl_xor_sync(0xffffffffu, a, 2);
            b2 += __shfl_xor_sync(0xffffffffu, b2, 1);
            b2 += __shfl_xor_sync(0xffffffffu, b2, 2);
            if(qi==0){
                int row = wm*32 + mt*16 + h*8 + q;
                red1[wn*64 + row] = a;
                red2[wn*64 + row] = b2;
            }
        }
    __syncthreads();
    if(tid < 64){
        float t1 = red1[tid] + red1[64+tid] + red1[128+tid] + red1[192+tid];
        float t2 = red2[tid] + red2[64+tid] + red2[128+tid] + red2[192+tid];
        float mu = t1*(1.0f/H);
        musm[tid] = mu;
        rssm[tid] = rsqrtf(t2*(1.0f/H) - mu*mu + 1e-5f);
    }
    __syncthreads();

    const float* lg = par + 192;
    const float* lb = par + 384;
    #pragma unroll
    for(int mt=0;mt<2;mt++)
        #pragma unroll
        for(int h=0;h<2;h++){
            int row = wm*32 + mt*16 + h*8 + q;
            float mu = musm[row], rs = rssm[row];
            float* xrow = g_x + (bt0+row)*H;
            __nv_bfloat16* yh = g_yh + (bt0+row)*H;
            __nv_bfloat16* yl = g_yl + (bt0+row)*H;
            #pragma unroll
            for(int nt=0;nt<6;nt++){
                int col = wn*48 + nt*8 + qi*2;
                float v0 = acc[mt][nt][h*2], v1 = acc[mt][nt][h*2+1];
                float2 res = *(float2*)(xrow + col);
                float o0 = gelu_exact((v0-mu)*rs*lg[col]   + lb[col])   + res.x;
                float o1 = gelu_exact((v1-mu)*rs*lg[col+1] + lb[col+1]) + res.y;
                *(float2*)(xrow + col) = make_float2(o0, o1);
                if(last){
                    __nv_bfloat16 h0 = __float2bfloat16(o0);
                    __nv_bfloat16 h1 = __float2bfloat16(o1);
                    __nv_bfloat16 l0 = __float2bfloat16(o0 - __bfloat162float(h0));
                    __nv_bfloat16 l1 = __float2bfloat16(o1 - __bfloat162float(h1));
                    __nv_bfloat162 ph = __halves2bfloat162(h0,h1);
                    __nv_bfloat162 pl = __halves2bfloat162(l0,l1);
                    *(__nv_bfloat162*)(yh + col) = ph;
                    *(__nv_bfloat162*)(yl + col) = pl;
                }
            }
        }
}

// ---------------------------------------------------------------------------
// spline: P = x_final . proj_w^T via split-bf16 mma, then RQ spline + logdet
#define SP_PWHI 0
#define SP_PWLO 12800
#define SP_ABUF 25600
#define SP_P    25600
#define SPLINE_SMEM_BYTES (25600 + 2*40960)

__global__ void __launch_bounds__(256) k_spline(
    const float* __restrict__ x, const float* __restrict__ xmask,
    const float* __restrict__ proj_b,
    float* __restrict__ out)
{
    extern __shared__ char smem[];
    uint32_t sbase = smem_u32(smem);
    int tid = threadIdx.x;
    int wid = tid >> 5, lane = tid & 31;
    int q = lane >> 2, qi = lane & 3;
    long long bt0 = (long long)blockIdx.x * 256;

    {
        const uint4* src = (const uint4*)g_pw;
        uint4* dst = (uint4*)smem;
        #pragma unroll
        for(int i=tid;i<1600;i+=256) dst[i] = src[i];
    }

    int rows[4], segs[4];
    #pragma unroll
    for(int m=0;m<4;m++){
        int id = tid + m*256;
        rows[m] = id >> 2; segs[m] = id & 3;
    }

#define SP_ISSUE(cc, st) do { \
    uint32_t _ah = sbase + SP_ABUF + (st)*40960; \
    uint32_t _al = _ah + 20480; \
    int _k = (cc)*32; \
    _Pragma("unroll") \
    for(int m=0;m<4;m++){ \
        uint32_t d = (uint32_t)rows[m]*80 + (uint32_t)segs[m]*16; \
        CP16(_ah + d, g_yh + (bt0+rows[m])*H + segs[m]*8 + _k); \
        CP16(_al + d, g_yl + (bt0+rows[m])*H + segs[m]*8 + _k); \
    } \
    CP_COMMIT; \
} while(0)

    SP_ISSUE(0, 0);
    SP_ISSUE(1, 1);

    int g2 = lane >> 3, lr = lane & 7;
    uint32_t aOff[2];
    #pragma unroll
    for(int mt=0;mt<2;mt++)
        aOff[mt] = (uint32_t)(wid*32 + mt*16 + (g2&1)*8 + lr)*80 + (uint32_t)(g2>>1)*16;
    uint32_t bOff[2];
    #pragma unroll
    for(int i=0;i<2;i++)
        bOff[i] = (uint32_t)(i*16 + (g2>>1)*8 + lr)*400 + (uint32_t)(g2&1)*16;

    float acc[2][4][4];
    #pragma unroll
    for(int mt=0;mt<2;mt++)
        #pragma unroll
        for(int nt=0;nt<4;nt++)
            #pragma unroll
            for(int r=0;r<4;r++) acc[mt][nt][r]=0.f;

    #pragma unroll 1
    for(int c=0;c<6;c++){
        if(c<5){ CP_WAIT1; } else { CP_WAIT0; }
        __syncthreads();
        uint32_t abufH = sbase + SP_ABUF + (c&1)*40960;
        uint32_t abufL = abufH + 20480;
        #pragma unroll
        for(int ks=0;ks<2;ks++){
            uint32_t kA = ks*32;
            uint32_t kB = (uint32_t)c*64 + ks*32;
            uint32_t ah[2][4], al[2][4], bb[2][4];
            LDSM4(ah[0], abufH + aOff[0] + kA);
            LDSM4(ah[1], abufH + aOff[1] + kA);
            LDSM4(al[0], abufL + aOff[0] + kA);
            LDSM4(al[1], abufL + aOff[1] + kA);
            LDSM4(bb[0], sbase + SP_PWHI + bOff[0] + kB);
            LDSM4(bb[1], sbase + SP_PWHI + bOff[1] + kB);
            #pragma unroll
            for(int mt=0;mt<2;mt++)
                #pragma unroll
                for(int i=0;i<2;i++){
                    MMA16816(acc[mt][2*i],   ah[mt], bb[i][0], bb[i][1]);
                    MMA16816(acc[mt][2*i+1], ah[mt], bb[i][2], bb[i][3]);
                }
            #pragma unroll
            for(int mt=0;mt<2;mt++)
                #pragma unroll
                for(int i=0;i<2;i++){
                    MMA16816(acc[mt][2*i],   al[mt], bb[i][0], bb[i][1]);
                    MMA16816(acc[mt][2*i+1], al[mt], bb[i][2], bb[i][3]);
                }
            LDSM4(bb[0], sbase + SP_PWLO + bOff[0] + kB);
            LDSM4(bb[1], sbase + SP_PWLO + bOff[1] + kB);
            #pragma unroll
            for(int mt=0;mt<2;mt++)
                #pragma unroll
                for(int i=0;i<2;i++){
                    MMA16816(acc[mt][2*i],   ah[mt], bb[i][0], bb[i][1]);
                    MMA16816(acc[mt][2*i+1], ah[mt], bb[i][2], bb[i][3]);
                }
        }
        __syncthreads();
        if(c<4) SP_ISSUE(c+2, c&1);
    }

    float* Psm = (float*)(smem + SP_P);
    #pragma unroll
    for(int mt=0;mt<2;mt++)
        #pragma unroll
        for(int h=0;h<2;h++){
            int row = wid*32 + mt*16 + h*8 + q;
            #pragma unroll
            for(int nt=0;nt<4;nt++){
                int col = nt*8 + qi*2;
                Psm[row*33 + col]   = acc[mt][nt][h*2];
                Psm[row*33 + col+1] = acc[mt][nt][h*2+1];
            }
        }
    __syncthreads();

    int b = (int)(bt0 >> 13);
    int t = (int)(bt0 & (T-1)) + tid;
    float mask = xmask[(long long)b*T + t];

    float p[NJ];
    #pragma unroll
    for(int j=0;j<NJ;j++) p[j] = (Psm[tid*33 + j] + __ldg(proj_b + j)) * mask;

    const float inv_dn = 0.07216878364870323f;   // 1/sqrt(192)

    float cwv[BINS+1], wsv[BINS];
    {
        float m = -1e30f;
        #pragma unroll
        for(int j=0;j<BINS;j++) m = fmaxf(m, p[j]);
        float e[BINS]; float ssum = 0.f;
        #pragma unroll
        for(int j=0;j<BINS;j++){ e[j] = expf((p[j]-m)*inv_dn); ssum += e[j]; }
        float inv = 1.0f/ssum;
        float cum = 0.f;
        cwv[0] = -TAILV;
        #pragma unroll
        for(int j=0;j<BINS;j++){
            float wj = 1e-3f + 0.99f*e[j]*inv;
            cum += wj;
            cwv[j+1] = 2.0f*TAILV*cum - TAILV;
        }
        cwv[BINS] = TAILV;
        #pragma unroll
        for(int j=0;j<BINS;j++) wsv[j] = cwv[j+1]-cwv[j];
    }
    float chv[BINS+1], hsv[BINS];
    {
        float m = -1e30f;
        #pragma unroll
        for(int j=0;j<BINS;j++) m = fmaxf(m, p[BINS+j]);
        float e[BINS]; float ssum = 0.f;
        #pragma unroll
        for(int j=0;j<BINS;j++){ e[j] = expf((p[BINS+j]-m)*inv_dn); ssum += e[j]; }
        float inv = 1.0f/ssum;
        float cum = 0.f;
        chv[0] = -TAILV;
        #pragma unroll
        for(int j=0;j<BINS;j++){
            float hj = 1e-3f + 0.99f*e[j]*inv;
            cum += hj;
            chv[j+1] = 2.0f*TAILV*cum - TAILV;
        }
        chv[BINS] = TAILV;
        #pragma unroll
        for(int j=0;j<BINS;j++) hsv[j] = chv[j+1]-chv[j];
    }
    float derv[BINS+1];
    derv[0] = 1.0f; derv[BINS] = 1.0f;
    #pragma unroll
    for(int k=1;k<BINS;k++){
        float u = p[2*BINS + k - 1];
        float sp = (u > 20.f) ? u : log1pf(expf(u));
        derv[k] = 1e-3f + sp;
    }

    float xbv = x[((long long)b*2+1)*T + t];
    bool inside = (xbv >= -TAILV) && (xbv <= TAILV);
    float xc = fminf(fmaxf(xbv, -TAILV), TAILV);
    int idx = 0;
    #pragma unroll
    for(int j=0;j<BINS;j++) idx += (xc >= cwv[j]) ? 1 : 0;
    idx -= 1;
    idx = max(0, min(BINS-1, idx));

    float icw=0.f, ibw=1.f, ich=0.f, ih=1.f, dk=1.f, dk1=1.f;
    #pragma unroll
    for(int j=0;j<BINS;j++){
        bool sel = (idx==j);
        icw = sel ? cwv[j]   : icw;
        ibw = sel ? wsv[j]   : ibw;
        ich = sel ? chv[j]   : ich;
        ih  = sel ? hsv[j]   : ih;
        dk  = sel ? derv[j]  : dk;
        dk1 = sel ? derv[j+1]: dk1;
    }

    float idl = ih/ibw;
    float th  = (xc - icw)/ibw;
    float t1m = th*(1.0f - th);
    float num = ih*(idl*th*th + dk*t1m);
    float den = idl + (dk + dk1 - 2.0f*idl)*t1m;
    float outv = ich + num/den;
    float omt = 1.0f - th;
    float dnum = idl*idl*(dk1*th*th + 2.0f*idl*t1m + dk*omt*omt);
    float lad = logf(dnum) - 2.0f*logf(den);

    float xb2 = inside ? outv : xbv;
    lad = inside ? lad : 0.0f;

    float xav = x[((long long)b*2)*T + t];
    out[(long long)b*2*T + t]     = xav*mask;
    out[(long long)b*2*T + T + t] = xb2*mask;

    float lv = lad*mask;
    #pragma unroll
    for(int o=16;o>0;o>>=1) lv += __shfl_xor_sync(0xffffffffu, lv, o);
    static __shared__ float red8[8];
    if(lane == 0) red8[wid] = lv;
    __syncthreads();
    if(tid == 0){
        float acc8 = red8[0]+red8[1]+red8[2]+red8[3]+red8[4]+red8[5]+red8[6]+red8[7];
        atomicAdd(out + (long long)B*2*T + b, acc8);
    }
}

// ---------------------------------------------------------------------------
extern "C" void kernel_launch(void* const* d_in, const int* in_sizes, int n_in,
                              void* d_out, int out_size)
{
    const float* x      = (const float*)d_in[0];
    const float* xmask  = (const float*)d_in[1];
    const float* in_w   = (const float*)d_in[2];
    const float* in_b   = (const float*)d_in[3];
    const float* dw_w   = (const float*)d_in[4];
    const float* dw_b   = (const float*)d_in[5];
    const float* ln1_g  = (const float*)d_in[6];
    const float* ln1_b  = (const float*)d_in[7];
    const float* pw_w   = (const float*)d_in[8];
    const float* pw_b   = (const float*)d_in[9];
    const float* ln2_g  = (const float*)d_in[10];
    const float* ln2_b  = (const float*)d_in[11];
    const float* proj_w = (const float*)d_in[12];
    const float* proj_b = (const float*)d_in[13];
    float* out = (float*)d_out;

    cudaFuncSetAttribute(k_gemm_mma, cudaFuncAttributeMaxDynamicSharedMemorySize, GEMM_SMEM_BYTES);
    cudaFuncSetAttribute(k_spline,   cudaFuncAttributeMaxDynamicSharedMemorySize, SPLINE_SMEM_BYTES);

    k_zero<<<1, 32>>>(out);
    k_prep<<<(3*H*H + 255)/256, 256>>>(pw_w, proj_w, dw_w);
    int dil = 1;
    for(int L=0; L<3; L++){
        k_conv<<<BT/32, 256>>>(L, dil, x, in_w, in_b, xmask, dw_b, ln1_g, ln1_b);
        k_gemm_mma<<<BT/64, 256, GEMM_SMEM_BYTES>>>(L, (L==2)?1:0, pw_b, ln2_g, ln2_b);
        dil *= 3;
    }
    k_spline<<<BT/256, 256, SPLINE_SMEM_BYTES>>>(x, xmask, proj_b, out);
}

// round 9
// speedup vs baseline: 1.2201x; 1.0885x over previous
#include <cuda_runtime.h>
#include <cuda_bf16.h>
#include <math.h>
#include <stdint.h>

#define B 32
#define T 8192
#define H 192
#define BT (B*T)
#define BINS 10
#define TAILV 5.0f
#define NJ 29

// residual stream ping-pong buffers (f32), layout [b][t][c]
__device__ float g_x0[(size_t)BT*H];
__device__ float g_x1[(size_t)BT*H];
// split bf16 streams of FINAL residual (for spline)
__device__ __align__(16) __nv_bfloat16 g_yh[(size_t)BT*H];
__device__ __align__(16) __nv_bfloat16 g_yl[(size_t)BT*H];
// chunk-ordered pw weight image: [layer][chunk12][dtype2][o192][seg2][8bf16]
__device__ __align__(16) __nv_bfloat16 g_wr[3*12*2*192*16];
// padded proj weight image: [hi/lo][32][pad 200] bf16
__device__ __align__(16) __nv_bfloat16 g_pw[2*32*200];
// transposed depthwise weights: [layer][tap][c]
__device__ float g_dwt[3*3*192];

__device__ __forceinline__ float gelu_exact(float v){
    return 0.5f*v*(1.0f+erff(v*0.70710678118654752f));
}

__device__ __forceinline__ uint32_t smem_u32(const void* p){
    uint32_t a;
    asm("{ .reg .u64 t; cvta.to.shared.u64 t, %1; cvt.u32.u64 %0, t; }" : "=r"(a) : "l"(p));
    return a;
}

#define LDSM4(r, addr) \
    asm volatile("ldmatrix.sync.aligned.m8n8.x4.shared.b16 {%0,%1,%2,%3}, [%4];" \
        : "=r"((r)[0]),"=r"((r)[1]),"=r"((r)[2]),"=r"((r)[3]) : "r"(addr))

#define MMA16816(d, a, b0, b1) \
    asm volatile("mma.sync.aligned.m16n8k16.row.col.f32.bf16.bf16.f32 " \
        "{%0,%1,%2,%3},{%4,%5,%6,%7},{%8,%9},{%0,%1,%2,%3};" \
        : "+f"((d)[0]),"+f"((d)[1]),"+f"((d)[2]),"+f"((d)[3]) \
        : "r"((a)[0]),"r"((a)[1]),"r"((a)[2]),"r"((a)[3]), "r"(b0),"r"(b1))

#define CP16(dst, src) \
    asm volatile("cp.async.cg.shared.global [%0], [%1], 16;" :: "r"(dst), "l"(src))
#define CP_COMMIT asm volatile("cp.async.commit_group;" ::: "memory")
#define CP_WAIT2  asm volatile("cp.async.wait_group 2;" ::: "memory")
#define CP_WAIT1  asm volatile("cp.async.wait_group 1;" ::: "memory")
#define CP_WAIT0  asm volatile("cp.async.wait_group 0;" ::: "memory")

// ---------------------------------------------------------------------------
__global__ void k_zero(float* __restrict__ out){
    out[(long long)B*2*T + threadIdx.x] = 0.0f;
}

// prep: pw chunk-ordered split image (k=16 chunks), proj image, dw transpose
__global__ void k_prep(const float* __restrict__ pw_w,
                       const float* __restrict__ proj_w,
                       const float* __restrict__ dw_w)
{
    int i = blockIdx.x*256 + threadIdx.x;
    if (i < 3*H*H){
        int L = i / (H*H);
        int r = i - L*(H*H);
        int o = r / H, k = r - o*H;
        float w = pw_w[i];
        __nv_bfloat16 hb = __float2bfloat16(w);
        __nv_bfloat16 lb = __float2bfloat16(w - __bfloat162float(hb));
        int ch = k >> 4;
        int s  = (k >> 3) & 1;
        int j  = k & 7;
        size_t base = (((size_t)(L*12 + ch)*2)*192 + o)*16 + s*8 + j;
        g_wr[base]        = hb;          // dtype 0
        g_wr[base + 3072] = lb;          // dtype 1: +192*16
    }
    if (i < 2*32*200){
        int p = i / 6400;
        int rem = i - p*6400;
        int r = rem / 200, c = rem - r*200;
        float w = (r < NJ && c < H) ? proj_w[r*H + c] : 0.0f;
        __nv_bfloat16 hb = __float2bfloat16(w);
        __nv_bfloat16 lb = __float2bfloat16(w - __bfloat162float(hb));
        g_pw[i] = p ? lb : hb;
    }
    if (i < 3*3*H){
        int L = i / (3*H);
        int rem = i - L*(3*H);
        int c = rem / 3, k = rem - c*3;
        g_dwt[L*(3*H) + k*H + c] = dw_w[i];
    }
}

// ---------------------------------------------------------------------------
// FUSED kernel: conv(dil)+LN1+gelu (phase 1, into A smem) -> split-bf16 GEMM
// vs streamed W (4-stage cp.async ring, k=16 chunks) -> bias+LN2+gelu+residual.
// 256 threads (2M x 4N warps), 64 t-rows per CTA, 2 CTAs/SM.
#define A_HI   0
#define A_LO   24576
#define BOFF   49152
#define BSTG   12288
#define PAR_OFF (BOFF + 4*BSTG)        // 98304
#define FUSED_SMEM_BYTES (PAR_OFF + 2304)

__global__ void __launch_bounds__(256,2) k_fused(int layer, int dil,
    const float* __restrict__ x,
    const float* __restrict__ in_w, const float* __restrict__ in_b,
    const float* __restrict__ xmask,
    const float* __restrict__ dw_b,
    const float* __restrict__ ln1_g, const float* __restrict__ ln1_b,
    const float* __restrict__ pw_b,
    const float* __restrict__ ln2_g, const float* __restrict__ ln2_b)
{
    extern __shared__ char smem[];
    uint32_t sbase = smem_u32(smem);
    int tid = threadIdx.x;
    int wid = tid >> 5, lane = tid & 31;
    int wm = wid & 1, wn = wid >> 1;          // 2 warps in M, 4 in N
    int q = lane >> 2, qi = lane & 3;
    long long bt0 = (long long)blockIdx.x * 64;
    int b  = (int)(bt0 >> 13);
    int t0 = (int)(bt0 & (T-1));
    bool first = (layer == 0), last = (layer == 2);
    const float* gin = last ? g_x1 : g_x0;    // L1 reads g_x0, L2 reads g_x1
    float* gout = first ? g_x0 : g_x1;        // L0 writes g_x0, L1 writes g_x1

    // B loader setup: 768 16B segs per chunk, 3 per thread
    uint32_t dstB[3];
    #pragma unroll
    for(int m=0;m<3;m++){
        int id = tid + m*256;
        int d = id / 384;
        int rem = id - d*384;
        int o = rem >> 1, s = rem & 1;
        dstB[m] = (uint32_t)d*6144 + (uint32_t)o*32
                + (uint32_t)((s ^ ((o>>2)&1)) << 4);
    }
    const uint4* wrp = (const uint4*)g_wr + (size_t)layer*9216 + tid;

#define ISSUE(cc, st) do { \
    uint32_t _bs = sbase + BOFF + (uint32_t)(st)*BSTG; \
    const uint4* _w = wrp + (cc)*768; \
    CP16(_bs + dstB[0], _w); \
    CP16(_bs + dstB[1], _w + 256); \
    CP16(_bs + dstB[2], _w + 512); \
    CP_COMMIT; \
} while(0)

    ISSUE(0, 0);
    ISSUE(1, 1);
    ISSUE(2, 2);

    // params
    float* par = (float*)(smem + PAR_OFF);
    if(tid < 192){
        par[tid]       = pw_b[layer*H + tid];
        par[192 + tid] = ln2_g[layer*H + tid];
        par[384 + tid] = ln2_b[layer*H + tid];
    }

    // ---------------- phase 1: conv + LN1 + gelu -> A smem ----------------
    {
        int c0 = lane*6;
        float w0[6], w1[6], w2[6], bbv[6], ggv[6], gbv[6];
        const float* wt = g_dwt + layer*(3*H);
        #pragma unroll
        for(int p=0;p<3;p++){
            float2 a = *(const float2*)(wt + c0 + p*2);
            w0[p*2]=a.x; w0[p*2+1]=a.y;
            float2 bq = *(const float2*)(wt + H + c0 + p*2);
            w1[p*2]=bq.x; w1[p*2+1]=bq.y;
            float2 cq = *(const float2*)(wt + 2*H + c0 + p*2);
            w2[p*2]=cq.x; w2[p*2+1]=cq.y;
            float2 d = *(const float2*)(dw_b + layer*H + c0 + p*2);
            bbv[p*2]=d.x; bbv[p*2+1]=d.y;
            float2 e = *(const float2*)(ln1_g + layer*H + c0 + p*2);
            ggv[p*2]=e.x; ggv[p*2+1]=e.y;
            float2 f = *(const float2*)(ln1_b + layer*H + c0 + p*2);
            gbv[p*2]=f.x; gbv[p*2+1]=f.y;
        }
        float iw[6], ib[6];
        if(first){
            #pragma unroll
            for(int p=0;p<3;p++){
                float2 a = *(const float2*)(in_w + c0 + p*2);
                iw[p*2]=a.x; iw[p*2+1]=a.y;
                float2 bq = *(const float2*)(in_b + c0 + p*2);
                ib[p*2]=bq.x; ib[p*2+1]=bq.y;
            }
        }
        const float* mrow = xmask + (long long)b*T;
        const float* xrowa = x + ((long long)b*2)*T;

        #pragma unroll 1
        for(int rr=0; rr<8; rr++){
            int r = wid*8 + rr;                 // local row 0..63
            long long grow = bt0 + r;
            int t = t0 + r;
            int tm = t - dil, tp = t + dil;
            bool hm = (tm >= 0), hp = (tp < T);
            float mm = hm ? mrow[tm] : 0.f;
            float m0 = mrow[t];
            float mp = hp ? mrow[tp] : 0.f;

            float xm[6], xz[6], xp[6];
            if(first){
                float xam = hm ? xrowa[tm] : 0.f;
                float xa0 = xrowa[t];
                float xap = hp ? xrowa[tp] : 0.f;
                #pragma unroll
                for(int k=0;k<6;k++){
                    xm[k] = iw[k]*xam + ib[k];
                    xz[k] = iw[k]*xa0 + ib[k];
                    xp[k] = iw[k]*xap + ib[k];
                }
            } else {
                const float* base = gin + grow*H + c0;
                #pragma unroll
                for(int p=0;p<3;p++){
                    float2 a = *(const float2*)(base + p*2);
                    xz[p*2]=a.x; xz[p*2+1]=a.y;
                }
                if(hm){
                    const float* bmp = base - (long long)dil*H;
                    #pragma unroll
                    for(int p=0;p<3;p++){
                        float2 a = *(const float2*)(bmp + p*2);
                        xm[p*2]=a.x; xm[p*2+1]=a.y;
                    }
                } else {
                    #pragma unroll
                    for(int k=0;k<6;k++) xm[k]=0.f;
                }
                if(hp){
                    const float* bpp = base + (long long)dil*H;
                    #pragma unroll
                    for(int p=0;p<3;p++){
                        float2 a = *(const float2*)(bpp + p*2);
                        xp[p*2]=a.x; xp[p*2+1]=a.y;
                    }
                } else {
                    #pragma unroll
                    for(int k=0;k<6;k++) xp[k]=0.f;
                }
            }

            float v[6];
            float s=0.f, sq=0.f;
            #pragma unroll
            for(int k=0;k<6;k++){
                float rv = w0[k]*(xm[k]*mm) + w1[k]*(xz[k]*m0) + w2[k]*(xp[k]*mp) + bbv[k];
                v[k]=rv; s+=rv; sq+=rv*rv;
            }
            #pragma unroll
            for(int o=16;o>0;o>>=1){
                s  += __shfl_xor_sync(0xffffffffu, s,  o);
                sq += __shfl_xor_sync(0xffffffffu, sq, o);
            }
            float mu = s*(1.0f/H);
            float rs = rsqrtf(sq*(1.0f/H) - mu*mu + 1e-5f);

            int xr = (r>>2)&1;
            #pragma unroll
            for(int p=0;p<3;p++){
                float y0 = gelu_exact((v[p*2]  -mu)*rs*ggv[p*2]   + gbv[p*2]);
                float y1 = gelu_exact((v[p*2+1]-mu)*rs*ggv[p*2+1] + gbv[p*2+1]);
                __nv_bfloat16 h0 = __float2bfloat16(y0);
                __nv_bfloat16 h1 = __float2bfloat16(y1);
                __nv_bfloat16 l0 = __float2bfloat16(y0 - __bfloat162float(h0));
                __nv_bfloat16 l1 = __float2bfloat16(y1 - __bfloat162float(h1));
                __nv_bfloat162 ph = __halves2bfloat162(h0,h1);
                __nv_bfloat162 pl = __halves2bfloat162(l0,l1);
                int c = c0 + 2*p;
                uint32_t off = (uint32_t)(c>>4)*2048 + (uint32_t)r*32
                             + (uint32_t)((((c>>3)&1) ^ xr) << 4) + (uint32_t)(c&7)*2;
                *(uint32_t*)(smem + A_HI + off) = *(uint32_t*)&ph;
                *(uint32_t*)(smem + A_LO + off) = *(uint32_t*)&pl;
            }
        }
    }

    // ---------------- phase 2: k-loop (12 chunks of k=16) ----------------
    int g2 = lane >> 3, lr = lane & 7;
    uint32_t aOff[2];
    #pragma unroll
    for(int mt=0;mt<2;mt++){
        int row = wm*32 + mt*16 + (g2&1)*8 + lr;
        aOff[mt] = (uint32_t)row*32 + (uint32_t)(((g2>>1) ^ ((row>>2)&1)) << 4);
    }
    uint32_t bOff[3];
    #pragma unroll
    for(int i=0;i<3;i++){
        int o = wn*48 + i*16 + (g2>>1)*8 + lr;
        bOff[i] = (uint32_t)o*32 + (uint32_t)(((g2&1) ^ ((o>>2)&1)) << 4);
    }

    float acc[2][6][4];
    #pragma unroll
    for(int mt=0;mt<2;mt++)
        #pragma unroll
        for(int nt=0;nt<6;nt++)
            #pragma unroll
            for(int r2=0;r2<4;r2++) acc[mt][nt][r2] = 0.f;

#define PASS(AH, BB) \
    _Pragma("unroll") \
    for(int mt=0;mt<2;mt++){ \
        _Pragma("unroll") \
        for(int i=0;i<3;i++){ \
            MMA16816(acc[mt][2*i],   AH[mt], BB[i][0], BB[i][1]); \
            MMA16816(acc[mt][2*i+1], AH[mt], BB[i][2], BB[i][3]); \
        } \
    }

    #pragma unroll 1
    for(int c=0;c<12;c++){
        if(c<10){ CP_WAIT2; } else if(c==10){ CP_WAIT1; } else { CP_WAIT0; }
        __syncthreads();
        if(c<9) ISSUE(c+3, (c+3)&3);
        uint32_t aB  = sbase + A_HI + (uint32_t)c*2048;
        uint32_t aBl = sbase + A_LO + (uint32_t)c*2048;
        uint32_t bB  = sbase + BOFF + (uint32_t)(c&3)*BSTG;

        uint32_t ah[2][4], al[2][4], bb[3][4];
        LDSM4(ah[0], aB  + aOff[0]);
        LDSM4(ah[1], aB  + aOff[1]);
        LDSM4(al[0], aBl + aOff[0]);
        LDSM4(al[1], aBl + aOff[1]);
        #pragma unroll
        for(int i=0;i<3;i++) LDSM4(bb[i], bB + bOff[i]);
        PASS(ah, bb)                               // Ah*Bh
        PASS(al, bb)                               // Al*Bh
        #pragma unroll
        for(int i=0;i<3;i++) LDSM4(bb[i], bB + 6144 + bOff[i]);
        PASS(ah, bb)                               // Ah*Bl
    }
#undef PASS

    // ---------------- epilogue: bias + LN2 + gelu + residual ----------------
    float* red1 = (float*)smem;        // overlay on A chunks 0-1 (dead)
    float* red2 = red1 + 256;
    float* musm = red1 + 512;
    float* rssm = red1 + 576;

    float s1[2][2] = {{0.f,0.f},{0.f,0.f}};
    float s2[2][2] = {{0.f,0.f},{0.f,0.f}};
    #pragma unroll
    for(int mt=0;mt<2;mt++)
        #pragma unroll
        for(int nt=0;nt<6;nt++){
            int col = wn*48 + nt*8 + qi*2;
            float b0 = par[col], b1 = par[col+1];
            acc[mt][nt][0] += b0; acc[mt][nt][1] += b1;
            acc[mt][nt][2] += b0; acc[mt][nt][3] += b1;
            #pragma unroll
            for(int h=0;h<2;h++){
                float v0 = acc[mt][nt][h*2], v1 = acc[mt][nt][h*2+1];
                s1[mt][h] += v0 + v1;
                s2[mt][h] += v0*v0 + v1*v1;
            }
        }
    __syncthreads();
    #pragma unroll
    for(int mt=0;mt<2;mt++)
        #pragma unroll
        for(int h=0;h<2;h++){
            float a = s1[mt][h], b2 = s2[mt][h];
            a  += __shfl_xor_sync(0xffffffffu, a, 1);
            a  += __shfl_xor_sync(0xffffffffu, a, 2);
            b2 += __shfl_xor_sync(0xffffffffu, b2, 1);
            b2 += __shfl_xor_sync(0xffffffffu, b2, 2);
            if(qi==0){
                int row = wm*32 + mt*16 + h*8 + q;
                red1[wn*64 + row] = a;
                red2[wn*64 + row] = b2;
            }
        }
    __syncthreads();
    if(tid < 64){
        float t1 = red1[tid] + red1[64+tid] + red1[128+tid] + red1[192+tid];
        float t2 = red2[tid] + red2[64+tid] + red2[128+tid] + red2[192+tid];
        float mu = t1*(1.0f/H);
        musm[tid] = mu;
        rssm[tid] = rsqrtf(t2*(1.0f/H) - mu*mu + 1e-5f);
    }
    __syncthreads();

    const float* lg = par + 192;
    const float* lb = par + 384;
    #pragma unroll
    for(int mt=0;mt<2;mt++)
        #pragma unroll
        for(int h=0;h<2;h++){
            int r = wm*32 + mt*16 + h*8 + q;
            float mu = musm[r], rs = rssm[r];
            long long grow = bt0 + r;
            float xa = 0.f;
            const float* ginrow = gin + grow*H;
            if(first) xa = x[((long long)b*2)*T + t0 + r];
            float* goutrow = gout + grow*H;
            __nv_bfloat16* yh = g_yh + grow*H;
            __nv_bfloat16* yl = g_yl + grow*H;
            #pragma unroll
            for(int nt=0;nt<6;nt++){
                int col = wn*48 + nt*8 + qi*2;
                float v0 = acc[mt][nt][h*2], v1 = acc[mt][nt][h*2+1];
                float res0, res1;
                if(first){
                    res0 = __ldg(in_w + col)*xa   + __ldg(in_b + col);
                    res1 = __ldg(in_w + col+1)*xa + __ldg(in_b + col+1);
                } else {
                    float2 rv = *(const float2*)(ginrow + col);
                    res0 = rv.x; res1 = rv.y;
                }
                float o0 = gelu_exact((v0-mu)*rs*lg[col]   + lb[col])   + res0;
                float o1 = gelu_exact((v1-mu)*rs*lg[col+1] + lb[col+1]) + res1;
                if(!last){
                    *(float2*)(goutrow + col) = make_float2(o0, o1);
                } else {
                    __nv_bfloat16 h0 = __float2bfloat16(o0);
                    __nv_bfloat16 h1 = __float2bfloat16(o1);
                    __nv_bfloat16 l0 = __float2bfloat16(o0 - __bfloat162float(h0));
                    __nv_bfloat16 l1 = __float2bfloat16(o1 - __bfloat162float(h1));
                    __nv_bfloat162 ph = __halves2bfloat162(h0,h1);
                    __nv_bfloat162 pl = __halves2bfloat162(l0,l1);
                    *(__nv_bfloat162*)(yh + col) = ph;
                    *(__nv_bfloat162*)(yl + col) = pl;
                }
            }
        }
}

// ---------------------------------------------------------------------------
// spline: P = x_final . proj_w^T via split-bf16 mma, then RQ spline + logdet
#define SP_PWHI 0
#define SP_PWLO 12800
#define SP_ABUF 25600
#define SP_P    25600
#define SPLINE_SMEM_BYTES (25600 + 2*40960)

__global__ void __launch_bounds__(256) k_spline(
    const float* __restrict__ x, const float* __restrict__ xmask,
    const float* __restrict__ proj_b,
    float* __restrict__ out)
{
    extern __shared__ char smem[];
    uint32_t sbase = smem_u32(smem);
    int tid = threadIdx.x;
    int wid = tid >> 5, lane = tid & 31;
    int q = lane >> 2, qi = lane & 3;
    long long bt0 = (long long)blockIdx.x * 256;

    {
        const uint4* src = (const uint4*)g_pw;
        uint4* dst = (uint4*)smem;
        #pragma unroll
        for(int i=tid;i<1600;i+=256) dst[i] = src[i];
    }

    int rows[4], segs[4];
    #pragma unroll
    for(int m=0;m<4;m++){
        int id = tid + m*256;
        rows[m] = id >> 2; segs[m] = id & 3;
    }

#define SP_ISSUE(cc, st) do { \
    uint32_t _ah = sbase + SP_ABUF + (st)*40960; \
    uint32_t _al = _ah + 20480; \
    int _k = (cc)*32; \
    _Pragma("unroll") \
    for(int m=0;m<4;m++){ \
        uint32_t d = (uint32_t)rows[m]*80 + (uint32_t)segs[m]*16; \
        CP16(_ah + d, g_yh + (bt0+rows[m])*H + segs[m]*8 + _k); \
        CP16(_al + d, g_yl + (bt0+rows[m])*H + segs[m]*8 + _k); \
    } \
    CP_COMMIT; \
} while(0)

    SP_ISSUE(0, 0);
    SP_ISSUE(1, 1);

    int g2 = lane >> 3, lr = lane & 7;
    uint32_t aOff[2];
    #pragma unroll
    for(int mt=0;mt<2;mt++)
        aOff[mt] = (uint32_t)(wid*32 + mt*16 + (g2&1)*8 + lr)*80 + (uint32_t)(g2>>1)*16;
    uint32_t bOff[2];
    #pragma unroll
    for(int i=0;i<2;i++)
        bOff[i] = (uint32_t)(i*16 + (g2>>1)*8 + lr)*400 + (uint32_t)(g2&1)*16;

    float acc[2][4][4];
    #pragma unroll
    for(int mt=0;mt<2;mt++)
        #pragma unroll
        for(int nt=0;nt<4;nt++)
            #pragma unroll
            for(int r=0;r<4;r++) acc[mt][nt][r]=0.f;

    #pragma unroll 1
    for(int c=0;c<6;c++){
        if(c<5){ CP_WAIT1; } else { CP_WAIT0; }
        __syncthreads();
        uint32_t abufH = sbase + SP_ABUF + (c&1)*40960;
        uint32_t abufL = abufH + 20480;
        #pragma unroll
        for(int ks=0;ks<2;ks++){
            uint32_t kA = ks*32;
            uint32_t kB = (uint32_t)c*64 + ks*32;
            uint32_t ah[2][4], al[2][4], bb[2][4];
            LDSM4(ah[0], abufH + aOff[0] + kA);
            LDSM4(ah[1], abufH + aOff[1] + kA);
            LDSM4(al[0], abufL + aOff[0] + kA);
            LDSM4(al[1], abufL + aOff[1] + kA);
            LDSM4(bb[0], sbase + SP_PWHI + bOff[0] + kB);
            LDSM4(bb[1], sbase + SP_PWHI + bOff[1] + kB);
            #pragma unroll
            for(int mt=0;mt<2;mt++)
                #pragma unroll
                for(int i=0;i<2;i++){
                    MMA16816(acc[mt][2*i],   ah[mt], bb[i][0], bb[i][1]);
                    MMA16816(acc[mt][2*i+1], ah[mt], bb[i][2], bb[i][3]);
                }
            #pragma unroll
            for(int mt=0;mt<2;mt++)
                #pragma unroll
                for(int i=0;i<2;i++){
                    MMA16816(acc[mt][2*i],   al[mt], bb[i][0], bb[i][1]);
                    MMA16816(acc[mt][2*i+1], al[mt], bb[i][2], bb[i][3]);
                }
            LDSM4(bb[0], sbase + SP_PWLO + bOff[0] + kB);
            LDSM4(bb[1], sbase + SP_PWLO + bOff[1] + kB);
            #pragma unroll
            for(int mt=0;mt<2;mt++)
                #pragma unroll
                for(int i=0;i<2;i++){
                    MMA16816(acc[mt][2*i],   ah[mt], bb[i][0], bb[i][1]);
                    MMA16816(acc[mt][2*i+1], ah[mt], bb[i][2], bb[i][3]);
                }
        }
        __syncthreads();
        if(c<4) SP_ISSUE(c+2, c&1);
    }

    float* Psm = (float*)(smem + SP_P);
    #pragma unroll
    for(int mt=0;mt<2;mt++)
        #pragma unroll
        for(int h=0;h<2;h++){
            int row = wid*32 + mt*16 + h*8 + q;
            #pragma unroll
            for(int nt=0;nt<4;nt++){
                int col = nt*8 + qi*2;
                Psm[row*33 + col]   = acc[mt][nt][h*2];
                Psm[row*33 + col+1] = acc[mt][nt][h*2+1];
            }
        }
    __syncthreads();

    int b = (int)(bt0 >> 13);
    int t = (int)(bt0 & (T-1)) + tid;
    float mask = xmask[(long long)b*T + t];

    float p[NJ];
    #pragma unroll
    for(int j=0;j<NJ;j++) p[j] = (Psm[tid*33 + j] + __ldg(proj_b + j)) * mask;

    const float inv_dn = 0.07216878364870323f;   // 1/sqrt(192)

    float cwv[BINS+1], wsv[BINS];
    {
        float m = -1e30f;
        #pragma unroll
        for(int j=0;j<BINS;j++) m = fmaxf(m, p[j]);
        float e[BINS]; float ssum = 0.f;
        #pragma unroll
        for(int j=0;j<BINS;j++){ e[j] = expf((p[j]-m)*inv_dn); ssum += e[j]; }
        float inv = 1.0f/ssum;
        float cum = 0.f;
        cwv[0] = -TAILV;
        #pragma unroll
        for(int j=0;j<BINS;j++){
            float wj = 1e-3f + 0.99f*e[j]*inv;
            cum += wj;
            cwv[j+1] = 2.0f*TAILV*cum - TAILV;
        }
        cwv[BINS] = TAILV;
        #pragma unroll
        for(int j=0;j<BINS;j++) wsv[j] = cwv[j+1]-cwv[j];
    }
    float chv[BINS+1], hsv[BINS];
    {
        float m = -1e30f;
        #pragma unroll
        for(int j=0;j<BINS;j++) m = fmaxf(m, p[BINS+j]);
        float e[BINS]; float ssum = 0.f;
        #pragma unroll
        for(int j=0;j<BINS;j++){ e[j] = expf((p[BINS+j]-m)*inv_dn); ssum += e[j]; }
        float inv = 1.0f/ssum;
        float cum = 0.f;
        chv[0] = -TAILV;
        #pragma unroll
        for(int j=0;j<BINS;j++){
            float hj = 1e-3f + 0.99f*e[j]*inv;
            cum += hj;
            chv[j+1] = 2.0f*TAILV*cum - TAILV;
        }
        chv[BINS] = TAILV;
        #pragma unroll
        for(int j=0;j<BINS;j++) hsv[j] = chv[j+1]-chv[j];
    }
    float derv[BINS+1];
    derv[0] = 1.0f; derv[BINS] = 1.0f;
    #pragma unroll
    for(int k=1;k<BINS;k++){
        float u = p[2*BINS + k - 1];
        float sp = (u > 20.f) ? u : log1pf(expf(u));
        derv[k] = 1e-3f + sp;
    }

    float xbv = x[((long long)b*2+1)*T + t];
    bool inside = (xbv >= -TAILV) && (xbv <= TAILV);
    float xc = fminf(fmaxf(xbv, -TAILV), TAILV);
    int idx = 0;
    #pragma unroll
    for(int j=0;j<BINS;j++) idx += (xc >= cwv[j]) ? 1 : 0;
    idx -= 1;
    idx = max(0, min(BINS-1, idx));

    float icw=0.f, ibw=1.f, ich=0.f, ih=1.f, dk=1.f, dk1=1.f;
    #pragma unroll
    for(int j=0;j<BINS;j++){
        bool sel = (idx==j);
        icw = sel ? cwv[j]   : icw;
        ibw = sel ? wsv[j]   : ibw;
        ich = sel ? chv[j]   : ich;
        ih  = sel ? hsv[j]   : ih;
        dk  = sel ? derv[j]  : dk;
        dk1 = sel ? derv[j+1]: dk1;
    }

    float idl = ih/ibw;
    float th  = (xc - icw)/ibw;
    float t1m = th*(1.0f - th);
    float num = ih*(idl*th*th + dk*t1m);
    float den = idl + (dk + dk1 - 2.0f*idl)*t1m;
    float outv = ich + num/den;
    float omt = 1.0f - th;
    float dnum = idl*idl*(dk1*th*th + 2.0f*idl*t1m + dk*omt*omt);
    float lad = logf(dnum) - 2.0f*logf(den);

    float xb2 = inside ? outv : xbv;
    lad = inside ? lad : 0.0f;

    float xav = x[((long long)b*2)*T + t];
    out[(long long)b*2*T + t]     = xav*mask;
    out[(long long)b*2*T + T + t] = xb2*mask;

    float lv = lad*mask;
    #pragma unroll
    for(int o=16;o>0;o>>=1) lv += __shfl_xor_sync(0xffffffffu, lv, o);
    static __shared__ float red8[8];
    if(lane == 0) red8[wid] = lv;
    __syncthreads();
    if(tid == 0){
        float acc8 = red8[0]+red8[1]+red8[2]+red8[3]+red8[4]+red8[5]+red8[6]+red8[7];
        atomicAdd(out + (long long)B*2*T + b, acc8);
    }
}

// ---------------------------------------------------------------------------
extern "C" void kernel_launch(void* const* d_in, const int* in_sizes, int n_in,
                              void* d_out, int out_size)
{
    const float* x      = (const float*)d_in[0];
    const float* xmask  = (const float*)d_in[1];
    const float* in_w   = (const float*)d_in[2];
    const float* in_b   = (const float*)d_in[3];
    const float* dw_w   = (const float*)d_in[4];
    const float* dw_b   = (const float*)d_in[5];
    const float* ln1_g  = (const float*)d_in[6];
    const float* ln1_b  = (const float*)d_in[7];
    const float* pw_w   = (const float*)d_in[8];
    const float* pw_b   = (const float*)d_in[9];
    const float* ln2_g  = (const float*)d_in[10];
    const float* ln2_b  = (const float*)d_in[11];
    const float* proj_w = (const float*)d_in[12];
    const float* proj_b = (const float*)d_in[13];
    float* out = (float*)d_out;

    cudaFuncSetAttribute(k_fused,  cudaFuncAttributeMaxDynamicSharedMemorySize, FUSED_SMEM_BYTES);
    cudaFuncSetAttribute(k_spline, cudaFuncAttributeMaxDynamicSharedMemorySize, SPLINE_SMEM_BYTES);

    k_zero<<<1, 32>>>(out);
    k_zero<<<1, 32>>>(out);          // dup: aligns ncu -s 5 onto fused L2
    k_prep<<<(3*H*H + 255)/256, 256>>>(pw_w, proj_w, dw_w);
    int dil = 1;
    for(int L=0; L<3; L++){
        k_fused<<<BT/64, 256, FUSED_SMEM_BYTES>>>(L, dil, x, in_w, in_b, xmask,
            dw_b, ln1_g, ln1_b, pw_b, ln2_g, ln2_b);
        dil *= 3;
    }
    k_spline<<<BT/256, 256, SPLINE_SMEM_BYTES>>>(x, xmask, proj_b, out);
}

// round 10
// speedup vs baseline: 1.3090x; 1.0728x over previous
#include <cuda_runtime.h>
#include <cuda_bf16.h>
#include <math.h>
#include <stdint.h>

#define B 32
#define T 8192
#define H 192
#define BT (B*T)
#define BINS 10
#define TAILV 5.0f
#define NJ 29

// residual stream ping-pong buffers (f32), layout [b][t][c]
__device__ float g_x0[(size_t)BT*H];
__device__ float g_x1[(size_t)BT*H];
// split bf16 streams of FINAL residual (for spline)
__device__ __align__(16) __nv_bfloat16 g_yh[(size_t)BT*H];
__device__ __align__(16) __nv_bfloat16 g_yl[(size_t)BT*H];
// chunk-ordered pw weight image: [layer][chunk12][dtype2][o192][seg2][8bf16]
__device__ __align__(16) __nv_bfloat16 g_wr[3*12*2*192*16];
// padded proj weight image: [hi/lo][32][pad 200] bf16
__device__ __align__(16) __nv_bfloat16 g_pw[2*32*200];
// transposed depthwise weights: [layer][tap][c]
__device__ float g_dwt[3*3*192];

// fast gelu: v - v/(exp(2c(v+av^3))+1); tails exact, |err|<~2e-4 abs
__device__ __forceinline__ float gelu_fast(float v){
    float t2 = 1.5957691216057308f * fmaf(0.044715f*v, v*v, v);
    float e = __expf(t2);
    float r;
    asm("rcp.approx.f32 %0, %1;" : "=f"(r) : "f"(e + 1.0f));
    return fmaf(-v, r, v);
}

// split (y0,y1) into packed bf16x2 hi + lo parts
__device__ __forceinline__ void split2(float y0, float y1, uint32_t& ph, uint32_t& pl){
    uint32_t h;
    asm("cvt.rn.bf16x2.f32 %0, %1, %2;" : "=r"(h) : "f"(y1), "f"(y0));
    float h0 = __uint_as_float(h << 16);
    float h1 = __uint_as_float(h & 0xffff0000u);
    asm("cvt.rn.bf16x2.f32 %0, %1, %2;" : "=r"(pl) : "f"(y1 - h1), "f"(y0 - h0));
    ph = h;
}

__device__ __forceinline__ uint32_t smem_u32(const void* p){
    uint32_t a;
    asm("{ .reg .u64 t; cvta.to.shared.u64 t, %1; cvt.u32.u64 %0, t; }" : "=r"(a) : "l"(p));
    return a;
}

#define LDSM4(r, addr) \
    asm volatile("ldmatrix.sync.aligned.m8n8.x4.shared.b16 {%0,%1,%2,%3}, [%4];" \
        : "=r"((r)[0]),"=r"((r)[1]),"=r"((r)[2]),"=r"((r)[3]) : "r"(addr))

#define MMA16816(d, a, b0, b1) \
    asm volatile("mma.sync.aligned.m16n8k16.row.col.f32.bf16.bf16.f32 " \
        "{%0,%1,%2,%3},{%4,%5,%6,%7},{%8,%9},{%0,%1,%2,%3};" \
        : "+f"((d)[0]),"+f"((d)[1]),"+f"((d)[2]),"+f"((d)[3]) \
        : "r"((a)[0]),"r"((a)[1]),"r"((a)[2]),"r"((a)[3]), "r"(b0),"r"(b1))

#define CP16(dst, src) \
    asm volatile("cp.async.cg.shared.global [%0], [%1], 16;" :: "r"(dst), "l"(src))
#define CP_COMMIT asm volatile("cp.async.commit_group;" ::: "memory")
#define CP_WAIT2  asm volatile("cp.async.wait_group 2;" ::: "memory")
#define CP_WAIT1  asm volatile("cp.async.wait_group 1;" ::: "memory")
#define CP_WAIT0  asm volatile("cp.async.wait_group 0;" ::: "memory")

// ---------------------------------------------------------------------------
__global__ void k_zero(float* __restrict__ out){
    out[(long long)B*2*T + threadIdx.x] = 0.0f;
}

// prep: pw chunk-ordered split image (k=16 chunks), proj image, dw transpose
__global__ void k_prep(const float* __restrict__ pw_w,
                       const float* __restrict__ proj_w,
                       const float* __restrict__ dw_w)
{
    int i = blockIdx.x*256 + threadIdx.x;
    if (i < 3*H*H){
        int L = i / (H*H);
        int r = i - L*(H*H);
        int o = r / H, k = r - o*H;
        float w = pw_w[i];
        __nv_bfloat16 hb = __float2bfloat16(w);
        __nv_bfloat16 lb = __float2bfloat16(w - __bfloat162float(hb));
        int ch = k >> 4;
        int s  = (k >> 3) & 1;
        int j  = k & 7;
        size_t base = (((size_t)(L*12 + ch)*2)*192 + o)*16 + s*8 + j;
        g_wr[base]        = hb;
        g_wr[base + 3072] = lb;
    }
    if (i < 2*32*200){
        int p = i / 6400;
        int rem = i - p*6400;
        int r = rem / 200, c = rem - r*200;
        float w = (r < NJ && c < H) ? proj_w[r*H + c] : 0.0f;
        __nv_bfloat16 hb = __float2bfloat16(w);
        __nv_bfloat16 lb = __float2bfloat16(w - __bfloat162float(hb));
        g_pw[i] = p ? lb : hb;
    }
    if (i < 3*3*H){
        int L = i / (3*H);
        int rem = i - L*(3*H);
        int c = rem / 3, k = rem - c*3;
        g_dwt[L*(3*H) + k*H + c] = dw_w[i];
    }
}

// ---------------------------------------------------------------------------
// FUSED kernel: conv(dil)+LN1+gelu (phase 1, into A smem) -> split-bf16 GEMM
// vs streamed W (4-stage cp.async ring, k=16 chunks) -> bias+LN2+gelu+residual.
#define A_HI   0
#define A_LO   24576
#define BOFF   49152
#define BSTG   12288
#define PAR_OFF (BOFF + 4*BSTG)        // 98304
#define FUSED_SMEM_BYTES (PAR_OFF + 2304)

__global__ void __launch_bounds__(256,2) k_fused(int layer, int dil,
    const float* __restrict__ x,
    const float* __restrict__ in_w, const float* __restrict__ in_b,
    const float* __restrict__ xmask,
    const float* __restrict__ dw_b,
    const float* __restrict__ ln1_g, const float* __restrict__ ln1_b,
    const float* __restrict__ pw_b,
    const float* __restrict__ ln2_g, const float* __restrict__ ln2_b)
{
    extern __shared__ char smem[];
    uint32_t sbase = smem_u32(smem);
    int tid = threadIdx.x;
    int wid = tid >> 5, lane = tid & 31;
    int wm = wid & 1, wn = wid >> 1;          // 2 warps in M, 4 in N
    int q = lane >> 2, qi = lane & 3;
    long long bt0 = (long long)blockIdx.x * 64;
    int b  = (int)(bt0 >> 13);
    int t0 = (int)(bt0 & (T-1));
    bool first = (layer == 0), last = (layer == 2);
    const float* gin = last ? g_x1 : g_x0;
    float* gout = first ? g_x0 : g_x1;

    uint32_t dstB[3];
    #pragma unroll
    for(int m=0;m<3;m++){
        int id = tid + m*256;
        int d = id / 384;
        int rem = id - d*384;
        int o = rem >> 1, s = rem & 1;
        dstB[m] = (uint32_t)d*6144 + (uint32_t)o*32
                + (uint32_t)((s ^ ((o>>2)&1)) << 4);
    }
    const uint4* wrp = (const uint4*)g_wr + (size_t)layer*9216 + tid;

#define ISSUE(cc, st) do { \
    uint32_t _bs = sbase + BOFF + (uint32_t)(st)*BSTG; \
    const uint4* _w = wrp + (cc)*768; \
    CP16(_bs + dstB[0], _w); \
    CP16(_bs + dstB[1], _w + 256); \
    CP16(_bs + dstB[2], _w + 512); \
    CP_COMMIT; \
} while(0)

    ISSUE(0, 0);
    ISSUE(1, 1);
    ISSUE(2, 2);

    float* par = (float*)(smem + PAR_OFF);
    if(tid < 192){
        par[tid]       = pw_b[layer*H + tid];
        par[192 + tid] = ln2_g[layer*H + tid];
        par[384 + tid] = ln2_b[layer*H + tid];
    }

    // ---------------- phase 1: conv + LN1 + gelu -> A smem ----------------
    {
        int c0 = lane*6;
        float w0[6], w1[6], w2[6], bbv[6], ggv[6], gbv[6];
        const float* wt = g_dwt + layer*(3*H);
        #pragma unroll
        for(int p=0;p<3;p++){
            float2 a = *(const float2*)(wt + c0 + p*2);
            w0[p*2]=a.x; w0[p*2+1]=a.y;
            float2 bq = *(const float2*)(wt + H + c0 + p*2);
            w1[p*2]=bq.x; w1[p*2+1]=bq.y;
            float2 cq = *(const float2*)(wt + 2*H + c0 + p*2);
            w2[p*2]=cq.x; w2[p*2+1]=cq.y;
            float2 d = *(const float2*)(dw_b + layer*H + c0 + p*2);
            bbv[p*2]=d.x; bbv[p*2+1]=d.y;
            float2 e = *(const float2*)(ln1_g + layer*H + c0 + p*2);
            ggv[p*2]=e.x; ggv[p*2+1]=e.y;
            float2 f = *(const float2*)(ln1_b + layer*H + c0 + p*2);
            gbv[p*2]=f.x; gbv[p*2+1]=f.y;
        }
        float iw[6], ib[6];
        if(first){
            #pragma unroll
            for(int p=0;p<3;p++){
                float2 a = *(const float2*)(in_w + c0 + p*2);
                iw[p*2]=a.x; iw[p*2+1]=a.y;
                float2 bq = *(const float2*)(in_b + c0 + p*2);
                ib[p*2]=bq.x; ib[p*2+1]=bq.y;
            }
        }
        const float* mrow = xmask + (long long)b*T;
        const float* xrowa = x + ((long long)b*2)*T;

        #pragma unroll 1
        for(int rr=0; rr<8; rr++){
            int r = wid*8 + rr;
            long long grow = bt0 + r;
            int t = t0 + r;
            int tm = t - dil, tp = t + dil;
            bool hm = (tm >= 0), hp = (tp < T);
            float mm = hm ? mrow[tm] : 0.f;
            float m0 = mrow[t];
            float mp = hp ? mrow[tp] : 0.f;

            float xm[6], xz[6], xp[6];
            if(first){
                float xam = hm ? xrowa[tm] : 0.f;
                float xa0 = xrowa[t];
                float xap = hp ? xrowa[tp] : 0.f;
                #pragma unroll
                for(int k=0;k<6;k++){
                    xm[k] = iw[k]*xam + ib[k];
                    xz[k] = iw[k]*xa0 + ib[k];
                    xp[k] = iw[k]*xap + ib[k];
                }
            } else {
                const float* base = gin + grow*H + c0;
                #pragma unroll
                for(int p=0;p<3;p++){
                    float2 a = *(const float2*)(base + p*2);
                    xz[p*2]=a.x; xz[p*2+1]=a.y;
                }
                if(hm){
                    const float* bmp = base - (long long)dil*H;
                    #pragma unroll
                    for(int p=0;p<3;p++){
                        float2 a = *(const float2*)(bmp + p*2);
                        xm[p*2]=a.x; xm[p*2+1]=a.y;
                    }
                } else {
                    #pragma unroll
                    for(int k=0;k<6;k++) xm[k]=0.f;
                }
                if(hp){
                    const float* bpp = base + (long long)dil*H;
                    #pragma unroll
                    for(int p=0;p<3;p++){
                        float2 a = *(const float2*)(bpp + p*2);
                        xp[p*2]=a.x; xp[p*2+1]=a.y;
                    }
                } else {
                    #pragma unroll
                    for(int k=0;k<6;k++) xp[k]=0.f;
                }
            }

            float v[6];
            float s=0.f, sq=0.f;
            #pragma unroll
            for(int k=0;k<6;k++){
                float rv = w0[k]*(xm[k]*mm) + w1[k]*(xz[k]*m0) + w2[k]*(xp[k]*mp) + bbv[k];
                v[k]=rv; s+=rv; sq+=rv*rv;
            }
            #pragma unroll
            for(int o=16;o>0;o>>=1){
                s  += __shfl_xor_sync(0xffffffffu, s,  o);
                sq += __shfl_xor_sync(0xffffffffu, sq, o);
            }
            float mu = s*(1.0f/H);
            float rs = rsqrtf(sq*(1.0f/H) - mu*mu + 1e-5f);

            int xr = (r>>2)&1;
            #pragma unroll
            for(int p=0;p<3;p++){
                float y0 = gelu_fast((v[p*2]  -mu)*rs*ggv[p*2]   + gbv[p*2]);
                float y1 = gelu_fast((v[p*2+1]-mu)*rs*ggv[p*2+1] + gbv[p*2+1]);
                uint32_t ph, pl;
                split2(y0, y1, ph, pl);
                int c = c0 + 2*p;
                uint32_t off = (uint32_t)(c>>4)*2048 + (uint32_t)r*32
                             + (uint32_t)((((c>>3)&1) ^ xr) << 4) + (uint32_t)(c&7)*2;
                *(uint32_t*)(smem + A_HI + off) = ph;
                *(uint32_t*)(smem + A_LO + off) = pl;
            }
        }
    }

    // ---------------- phase 2: k-loop (12 chunks of k=16) ----------------
    int g2 = lane >> 3, lr = lane & 7;
    uint32_t aOff[2];
    #pragma unroll
    for(int mt=0;mt<2;mt++){
        int row = wm*32 + mt*16 + (g2&1)*8 + lr;
        aOff[mt] = (uint32_t)row*32 + (uint32_t)(((g2>>1) ^ ((row>>2)&1)) << 4);
    }
    uint32_t bOff[3];
    #pragma unroll
    for(int i=0;i<3;i++){
        int o = wn*48 + i*16 + (g2>>1)*8 + lr;
        bOff[i] = (uint32_t)o*32 + (uint32_t)(((g2&1) ^ ((o>>2)&1)) << 4);
    }

    float acc[2][6][4];
    #pragma unroll
    for(int mt=0;mt<2;mt++)
        #pragma unroll
        for(int nt=0;nt<6;nt++)
            #pragma unroll
            for(int r2=0;r2<4;r2++) acc[mt][nt][r2] = 0.f;

#define PASS(AH, BB) \
    _Pragma("unroll") \
    for(int mt=0;mt<2;mt++){ \
        _Pragma("unroll") \
        for(int i=0;i<3;i++){ \
            MMA16816(acc[mt][2*i],   AH[mt], BB[i][0], BB[i][1]); \
            MMA16816(acc[mt][2*i+1], AH[mt], BB[i][2], BB[i][3]); \
        } \
    }

    #pragma unroll 1
    for(int c=0;c<12;c++){
        if(c<10){ CP_WAIT2; } else if(c==10){ CP_WAIT1; } else { CP_WAIT0; }
        __syncthreads();
        if(c<9) ISSUE(c+3, (c+3)&3);
        uint32_t aB  = sbase + A_HI + (uint32_t)c*2048;
        uint32_t aBl = sbase + A_LO + (uint32_t)c*2048;
        uint32_t bB  = sbase + BOFF + (uint32_t)(c&3)*BSTG;

        uint32_t ah[2][4], al[2][4], bb[3][4];
        LDSM4(ah[0], aB  + aOff[0]);
        LDSM4(ah[1], aB  + aOff[1]);
        LDSM4(al[0], aBl + aOff[0]);
        LDSM4(al[1], aBl + aOff[1]);
        #pragma unroll
        for(int i=0;i<3;i++) LDSM4(bb[i], bB + bOff[i]);
        PASS(ah, bb)                               // Ah*Bh
        PASS(al, bb)                               // Al*Bh
        #pragma unroll
        for(int i=0;i<3;i++) LDSM4(bb[i], bB + 6144 + bOff[i]);
        PASS(ah, bb)                               // Ah*Bl
    }
#undef PASS

    // ---------------- epilogue: bias + LN2 + gelu + residual ----------------
    float* red1 = (float*)smem;
    float* red2 = red1 + 256;
    float* musm = red1 + 512;
    float* rssm = red1 + 576;

    float s1[2][2] = {{0.f,0.f},{0.f,0.f}};
    float s2[2][2] = {{0.f,0.f},{0.f,0.f}};
    #pragma unroll
    for(int mt=0;mt<2;mt++)
        #pragma unroll
        for(int nt=0;nt<6;nt++){
            int col = wn*48 + nt*8 + qi*2;
            float b0 = par[col], b1 = par[col+1];
            acc[mt][nt][0] += b0; acc[mt][nt][1] += b1;
            acc[mt][nt][2] += b0; acc[mt][nt][3] += b1;
            #pragma unroll
            for(int h=0;h<2;h++){
                float v0 = acc[mt][nt][h*2], v1 = acc[mt][nt][h*2+1];
                s1[mt][h] += v0 + v1;
                s2[mt][h] += v0*v0 + v1*v1;
            }
        }
    __syncthreads();
    #pragma unroll
    for(int mt=0;mt<2;mt++)
        #pragma unroll
        for(int h=0;h<2;h++){
            float a = s1[mt][h], b2 = s2[mt][h];
            a  += __shfl_xor_sync(0xffffffffu, a, 1);
            a  += __shfl_xor_sync(0xffffffffu, a, 2);
            b2 += __shfl_xor_sync(0xffffffffu, b2, 1);
            b2 += __shfl_xor_sync(0xffffffffu, b2, 2);
            if(qi==0){
                int row = wm*32 + mt*16 + h*8 + q;
                red1[wn*64 + row] = a;
                red2[wn*64 + row] = b2;
            }
        }
    __syncthreads();
    if(tid < 64){
        float t1 = red1[tid] + red1[64+tid] + red1[128+tid] + red1[192+tid];
        float t2 = red2[tid] + red2[64+tid] + red2[128+tid] + red2[192+tid];
        float mu = t1*(1.0f/H);
        musm[tid] = mu;
        rssm[tid] = rsqrtf(t2*(1.0f/H) - mu*mu + 1e-5f);
    }
    __syncthreads();

    const float* lg = par + 192;
    const float* lb = par + 384;
    #pragma unroll
    for(int mt=0;mt<2;mt++)
        #pragma unroll
        for(int h=0;h<2;h++){
            int r = wm*32 + mt*16 + h*8 + q;
            float mu = musm[r], rs = rssm[r];
            long long grow = bt0 + r;
            float xa = 0.f;
            const float* ginrow = gin + grow*H;
            if(first) xa = x[((long long)b*2)*T + t0 + r];
            float* goutrow = gout + grow*H;
            __nv_bfloat16* yh = g_yh + grow*H;
            __nv_bfloat16* yl = g_yl + grow*H;
            #pragma unroll
            for(int nt=0;nt<6;nt++){
                int col = wn*48 + nt*8 + qi*2;
                float v0 = acc[mt][nt][h*2], v1 = acc[mt][nt][h*2+1];
                float res0, res1;
                if(first){
                    res0 = __ldg(in_w + col)*xa   + __ldg(in_b + col);
                    res1 = __ldg(in_w + col+1)*xa + __ldg(in_b + col+1);
                } else {
                    float2 rv = *(const float2*)(ginrow + col);
                    res0 = rv.x; res1 = rv.y;
                }
                float o0 = gelu_fast((v0-mu)*rs*lg[col]   + lb[col])   + res0;
                float o1 = gelu_fast((v1-mu)*rs*lg[col+1] + lb[col+1]) + res1;
                if(!last){
                    *(float2*)(goutrow + col) = make_float2(o0, o1);
                } else {
                    uint32_t ph, pl;
                    split2(o0, o1, ph, pl);
                    *(uint32_t*)(yh + col) = ph;
                    *(uint32_t*)(yl + col) = pl;
                }
            }
        }
}

// ---------------------------------------------------------------------------
// spline: P = x_final . proj_w^T via split-bf16 mma, then RQ spline + logdet
#define SP_PWHI 0
#define SP_PWLO 12800
#define SP_ABUF 25600
#define SP_P    25600
#define SPLINE_SMEM_BYTES (25600 + 2*40960)

__global__ void __launch_bounds__(256) k_spline(
    const float* __restrict__ x, const float* __restrict__ xmask,
    const float* __restrict__ proj_b,
    float* __restrict__ out)
{
    extern __shared__ char smem[];
    uint32_t sbase = smem_u32(smem);
    int tid = threadIdx.x;
    int wid = tid >> 5, lane = tid & 31;
    int q = lane >> 2, qi = lane & 3;
    long long bt0 = (long long)blockIdx.x * 256;

    {
        const uint4* src = (const uint4*)g_pw;
        uint4* dst = (uint4*)smem;
        #pragma unroll
        for(int i=tid;i<1600;i+=256) dst[i] = src[i];
    }

    int rows[4], segs[4];
    #pragma unroll
    for(int m=0;m<4;m++){
        int id = tid + m*256;
        rows[m] = id >> 2; segs[m] = id & 3;
    }

#define SP_ISSUE(cc, st) do { \
    uint32_t _ah = sbase + SP_ABUF + (st)*40960; \
    uint32_t _al = _ah + 20480; \
    int _k = (cc)*32; \
    _Pragma("unroll") \
    for(int m=0;m<4;m++){ \
        uint32_t d = (uint32_t)rows[m]*80 + (uint32_t)segs[m]*16; \
        CP16(_ah + d, g_yh + (bt0+rows[m])*H + segs[m]*8 + _k); \
        CP16(_al + d, g_yl + (bt0+rows[m])*H + segs[m]*8 + _k); \
    } \
    CP_COMMIT; \
} while(0)

    SP_ISSUE(0, 0);
    SP_ISSUE(1, 1);

    int g2 = lane >> 3, lr = lane & 7;
    uint32_t aOff[2];
    #pragma unroll
    for(int mt=0;mt<2;mt++)
        aOff[mt] = (uint32_t)(wid*32 + mt*16 + (g2&1)*8 + lr)*80 + (uint32_t)(g2>>1)*16;
    uint32_t bOff[2];
    #pragma unroll
    for(int i=0;i<2;i++)
        bOff[i] = (uint32_t)(i*16 + (g2>>1)*8 + lr)*400 + (uint32_t)(g2&1)*16;

    float acc[2][4][4];
    #pragma unroll
    for(int mt=0;mt<2;mt++)
        #pragma unroll
        for(int nt=0;nt<4;nt++)
            #pragma unroll
            for(int r=0;r<4;r++) acc[mt][nt][r]=0.f;

    #pragma unroll 1
    for(int c=0;c<6;c++){
        if(c<5){ CP_WAIT1; } else { CP_WAIT0; }
        __syncthreads();
        uint32_t abufH = sbase + SP_ABUF + (c&1)*40960;
        uint32_t abufL = abufH + 20480;
        #pragma unroll
        for(int ks=0;ks<2;ks++){
            uint32_t kA = ks*32;
            uint32_t kB = (uint32_t)c*64 + ks*32;
            uint32_t ah[2][4], al[2][4], bb[2][4];
            LDSM4(ah[0], abufH + aOff[0] + kA);
            LDSM4(ah[1], abufH + aOff[1] + kA);
            LDSM4(al[0], abufL + aOff[0] + kA);
            LDSM4(al[1], abufL + aOff[1] + kA);
            LDSM4(bb[0], sbase + SP_PWHI + bOff[0] + kB);
            LDSM4(bb[1], sbase + SP_PWHI + bOff[1] + kB);
            #pragma unroll
            for(int mt=0;mt<2;mt++)
                #pragma unroll
                for(int i=0;i<2;i++){
                    MMA16816(acc[mt][2*i],   ah[mt], bb[i][0], bb[i][1]);
                    MMA16816(acc[mt][2*i+1], ah[mt], bb[i][2], bb[i][3]);
                }
            #pragma unroll
            for(int mt=0;mt<2;mt++)
                #pragma unroll
                for(int i=0;i<2;i++){
                    MMA16816(acc[mt][2*i],   al[mt], bb[i][0], bb[i][1]);
                    MMA16816(acc[mt][2*i+1], al[mt], bb[i][2], bb[i][3]);
                }
            LDSM4(bb[0], sbase + SP_PWLO + bOff[0] + kB);
            LDSM4(bb[1], sbase + SP_PWLO + bOff[1] + kB);
            #pragma unroll
            for(int mt=0;mt<2;mt++)
                #pragma unroll
                for(int i=0;i<2;i++){
                    MMA16816(acc[mt][2*i],   ah[mt], bb[i][0], bb[i][1]);
                    MMA16816(acc[mt][2*i+1], ah[mt], bb[i][2], bb[i][3]);
                }
        }
        __syncthreads();
        if(c<4) SP_ISSUE(c+2, c&1);
    }

    float* Psm = (float*)(smem + SP_P);
    #pragma unroll
    for(int mt=0;mt<2;mt++)
        #pragma unroll
        for(int h=0;h<2;h++){
            int row = wid*32 + mt*16 + h*8 + q;
            #pragma unroll
            for(int nt=0;nt<4;nt++){
                int col = nt*8 + qi*2;
                Psm[row*33 + col]   = acc[mt][nt][h*2];
                Psm[row*33 + col+1] = acc[mt][nt][h*2+1];
            }
        }
    __syncthreads();

    int b = (int)(bt0 >> 13);
    int t = (int)(bt0 & (T-1)) + tid;
    float mask = xmask[(long long)b*T + t];

    float p[NJ];
    #pragma unroll
    for(int j=0;j<NJ;j++) p[j] = (Psm[tid*33 + j] + __ldg(proj_b + j)) * mask;

    const float inv_dn = 0.07216878364870323f;   // 1/sqrt(192)

    float cwv[BINS+1], wsv[BINS];
    {
        float m = -1e30f;
        #pragma unroll
        for(int j=0;j<BINS;j++) m = fmaxf(m, p[j]);
        float e[BINS]; float ssum = 0.f;
        #pragma unroll
        for(int j=0;j<BINS;j++){ e[j] = __expf((p[j]-m)*inv_dn); ssum += e[j]; }
        float inv = 1.0f/ssum;
        float cum = 0.f;
        cwv[0] = -TAILV;
        #pragma unroll
        for(int j=0;j<BINS;j++){
            float wj = 1e-3f + 0.99f*e[j]*inv;
            cum += wj;
            cwv[j+1] = 2.0f*TAILV*cum - TAILV;
        }
        cwv[BINS] = TAILV;
        #pragma unroll
        for(int j=0;j<BINS;j++) wsv[j] = cwv[j+1]-cwv[j];
    }
    float chv[BINS+1], hsv[BINS];
    {
        float m = -1e30f;
        #pragma unroll
        for(int j=0;j<BINS;j++) m = fmaxf(m, p[BINS+j]);
        float e[BINS]; float ssum = 0.f;
        #pragma unroll
        for(int j=0;j<BINS;j++){ e[j] = __expf((p[BINS+j]-m)*inv_dn); ssum += e[j]; }
        float inv = 1.0f/ssum;
        float cum = 0.f;
        chv[0] = -TAILV;
        #pragma unroll
        for(int j=0;j<BINS;j++){
            float hj = 1e-3f + 0.99f*e[j]*inv;
            cum += hj;
            chv[j+1] = 2.0f*TAILV*cum - TAILV;
        }
        chv[BINS] = TAILV;
        #pragma unroll
        for(int j=0;j<BINS;j++) hsv[j] = chv[j+1]-chv[j];
    }
    float derv[BINS+1];
    derv[0] = 1.0f; derv[BINS] = 1.0f;
    #pragma unroll
    for(int k=1;k<BINS;k++){
        float u = p[2*BINS + k - 1];
        float sp = (u > 20.f) ? u : __logf(1.0f + __expf(u));
        derv[k] = 1e-3f + sp;
    }

    float xbv = x[((long long)b*2+1)*T + t];
    bool inside = (xbv >= -TAILV) && (xbv <= TAILV);
    float xc = fminf(fmaxf(xbv, -TAILV), TAILV);
    int idx = 0;
    #pragma unroll
    for(int j=0;j<BINS;j++) idx += (xc >= cwv[j]) ? 1 : 0;
    idx -= 1;
    idx = max(0, min(BINS-1, idx));

    float icw=0.f, ibw=1.f, ich=0.f, ih=1.f, dk=1.f, dk1=1.f;
    #pragma unroll
    for(int j=0;j<BINS;j++){
        bool sel = (idx==j);
        icw = sel ? cwv[j]   : icw;
        ibw = sel ? wsv[j]   : ibw;
        ich = sel ? chv[j]   : ich;
        ih  = sel ? hsv[j]   : ih;
        dk  = sel ? derv[j]  : dk;
        dk1 = sel ? derv[j+1]: dk1;
    }

    float idl = ih/ibw;
    float th  = (xc - icw)/ibw;
    float t1m = th*(1.0f - th);
    float num = ih*(idl*th*th + dk*t1m);
    float den = idl + (dk + dk1 - 2.0f*idl)*t1m;
    float outv = ich + num/den;
    float omt = 1.0f - th;
    float dnum = idl*idl*(dk1*th*th + 2.0f*idl*t1m + dk*omt*omt);
    float lad = __logf(dnum) - 2.0f*__logf(den);

    float xb2 = inside ? outv : xbv;
    lad = inside ? lad : 0.0f;

    float xav = x[((long long)b*2)*T + t];
    out[(long long)b*2*T + t]     = xav*mask;
    out[(long long)b*2*T + T + t] = xb2*mask;

    float lv = lad*mask;
    #pragma unroll
    for(int o=16;o>0;o>>=1) lv += __shfl_xor_sync(0xffffffffu, lv, o);
    static __shared__ float red8[8];
    if(lane == 0) red8[wid] = lv;
    __syncthreads();
    if(tid == 0){
        float acc8 = red8[0]+red8[1]+red8[2]+red8[3]+red8[4]+red8[5]+red8[6]+red8[7];
        atomicAdd(out + (long long)B*2*T + b, acc8);
    }
}

// ---------------------------------------------------------------------------
extern "C" void kernel_launch(void* const* d_in, const int* in_sizes, int n_in,
                              void* d_out, int out_size)
{
    const float* x      = (const float*)d_in[0];
    const float* xmask  = (const float*)d_in[1];
    const float* in_w   = (const float*)d_in[2];
    const float* in_b   = (const float*)d_in[3];
    const float* dw_w   = (const float*)d_in[4];
    const float* dw_b   = (const float*)d_in[5];
    const float* ln1_g  = (const float*)d_in[6];
    const float* ln1_b  = (const float*)d_in[7];
    const float* pw_w   = (const float*)d_in[8];
    const float* pw_b   = (const float*)d_in[9];
    const float* ln2_g  = (const float*)d_in[10];
    const float* ln2_b  = (const float*)d_in[11];
    const float* proj_w = (const float*)d_in[12];
    const float* proj_b = (const float*)d_in[13];
    float* out = (float*)d_out;

    cudaFuncSetAttribute(k_fused,  cudaFuncAttributeMaxDynamicSharedMemorySize, FUSED_SMEM_BYTES);
    cudaFuncSetAttribute(k_spline, cudaFuncAttributeMaxDynamicSharedMemorySize, SPLINE_SMEM_BYTES);

    k_zero<<<1, 32>>>(out);
    k_zero<<<1, 32>>>(out);          // dup: aligns ncu -s 5 onto fused L2
    k_prep<<<(3*H*H + 255)/256, 256>>>(pw_w, proj_w, dw_w);
    int dil = 1;
    for(int L=0; L<3; L++){
        k_fused<<<BT/64, 256, FUSED_SMEM_BYTES>>>(L, dil, x, in_w, in_b, xmask,
            dw_b, ln1_g, ln1_b, pw_b, ln2_g, ln2_b);
        dil *= 3;
    }
    k_spline<<<BT/256, 256, SPLINE_SMEM_BYTES>>>(x, xmask, proj_b, out);
}